// round 1
// baseline (speedup 1.0000x reference)
#include <cuda_runtime.h>
#include <cuda_bf16.h>
#include <mma.h>
#include <math.h>

using namespace nvcuda;

#define VOCAB 32000
#define EMBED 512
#define HID   1024      // DEC_H
#define SEQL  64
#define BATCH 32
#define G4    4096      // 4*HID

// ---------------- device scratch (static: no allocs allowed) ----------------
__device__ float d_Eenc[SEQL * BATCH * EMBED];        // gathered encoder embeddings
__device__ float d_enc_outs[BATCH * SEQL * HID];      // [b][t][d]
__device__ float d_he[BATCH * HID], d_ce[BATCH * HID];
__device__ float d_hd[BATCH * HID], d_cd[BATCH * HID];
__device__ float d_gates[BATCH * G4];
__device__ float d_ebuf[BATCH * HID];
__device__ float d_ctx[BATCH * HID];
__device__ float d_inp[BATCH * HID];
__device__ float d_alog[BATCH * 128];
__device__ float d_abias[128];
__device__ float d_logits[(size_t)BATCH * VOCAB];

__device__ __nv_bfloat16 d_Wenc[(EMBED + HID) * G4];     // [enc_wx; enc_wh]
__device__ __nv_bfloat16 d_Wdec[(2 * HID) * G4];         // [dec_wx; dec_wh]
__device__ __nv_bfloat16 d_Wcomb[(2 * HID) * HID];
__device__ __nv_bfloat16 d_Wout[(size_t)HID * VOCAB];
__device__ __nv_bfloat16 d_Wattn[(2 * HID) * 128];       // attn_w padded 64->128 cols

// ---------------- helpers ----------------
__device__ __forceinline__ float sigm(float x) { return 1.f / (1.f + expf(-x)); }

// ---------------- weight conversion ----------------
__global__ void cvt_kernel(const float* __restrict__ src, __nv_bfloat16* __restrict__ dst, size_t n) {
    for (size_t i = (size_t)blockIdx.x * blockDim.x + threadIdx.x; i < n;
         i += (size_t)gridDim.x * blockDim.x)
        dst[i] = __float2bfloat16(src[i]);
}

__global__ void cvt_pad_attn_kernel(const float* __restrict__ src) {
    // src: [2048][64] -> d_Wattn [2048][128] (zero pad)
    size_t n = (size_t)(2 * HID) * 128;
    for (size_t i = (size_t)blockIdx.x * blockDim.x + threadIdx.x; i < n;
         i += (size_t)gridDim.x * blockDim.x) {
        int k = (int)(i >> 7), j = (int)(i & 127);
        d_Wattn[i] = (j < SEQL) ? __float2bfloat16(src[k * SEQL + j]) : __float2bfloat16(0.f);
    }
}

// zero states, init attn bias pad, gather initial decoder embedding (token 127)
__global__ void init_state_kernel(const float* __restrict__ attn_b, const float* __restrict__ dec_embed) {
    int i = blockIdx.x * blockDim.x + threadIdx.x;
    if (i < BATCH * HID) {
        d_he[i] = 0.f; d_ce[i] = 0.f; d_hd[i] = 0.f; d_cd[i] = 0.f;
        d_ebuf[i] = dec_embed[(size_t)127 * HID + (i % HID)];
    }
    if (i < 128) d_abias[i] = (i < SEQL) ? attn_b[i] : 0.f;
}

__global__ void gather_enc_kernel(const int* __restrict__ x, const float* __restrict__ enc_embed) {
    size_t n = (size_t)SEQL * BATCH * EMBED;
    for (size_t i = (size_t)blockIdx.x * blockDim.x + threadIdx.x; i < n;
         i += (size_t)gridDim.x * blockDim.x) {
        int t = (int)(i / (BATCH * EMBED));
        int r = (int)(i % (BATCH * EMBED));
        int b = r / EMBED, d = r % EMBED;
        int tok = x[b * SEQL + t];
        d_Eenc[i] = enc_embed[(size_t)tok * EMBED + d];
    }
}

// ---------------- generic small-M GEMM: C[32][N] = [A1|A2](fp32) @ B(bf16) + bias ----------------
// block = 256 threads, tile 32 x 128. 8 warps: warp -> (mh = w/4 in {0,1}, nq = w%4).
__global__ __launch_bounds__(256) void gemm32_kernel(
    const float* __restrict__ A1, int K1,
    const float* __restrict__ A2, int K2,
    const __nv_bfloat16* __restrict__ Bw, int N,
    const float* __restrict__ bias,
    float* __restrict__ C, int relu)
{
    __shared__ __align__(32) __nv_bfloat16 sA[32 * 16];
    __shared__ float sC[32 * 128];

    const int n0 = blockIdx.x * 128;
    const int w = threadIdx.x >> 5;
    const int mh = w >> 2, nq = w & 3;

    wmma::fragment<wmma::matrix_a, 16, 16, 16, __nv_bfloat16, wmma::row_major> fa;
    wmma::fragment<wmma::matrix_b, 16, 16, 16, __nv_bfloat16, wmma::row_major> fb0, fb1;
    wmma::fragment<wmma::accumulator, 16, 16, 16, float> acc0, acc1;
    wmma::fill_fragment(acc0, 0.f);
    wmma::fill_fragment(acc1, 0.f);

    const int K = K1 + K2;
    for (int k0 = 0; k0 < K; k0 += 16) {
        // stage A tile 32x16 fp32 -> bf16 in smem (2 elements/thread)
        int i = threadIdx.x;
        #pragma unroll
        for (int rep = 0; rep < 2; rep++, i += 256) {
            int m = i >> 4, kk = i & 15;
            int k = k0 + kk;
            float v = (k < K1) ? A1[m * K1 + k] : A2[m * K2 + (k - K1)];
            sA[m * 16 + kk] = __float2bfloat16(v);
        }
        __syncthreads();
        wmma::load_matrix_sync(fa, sA + mh * 16 * 16, 16);
        const __nv_bfloat16* bp = Bw + (size_t)k0 * N + n0 + nq * 32;
        wmma::load_matrix_sync(fb0, bp, N);
        wmma::load_matrix_sync(fb1, bp + 16, N);
        wmma::mma_sync(acc0, fa, fb0, acc0);
        wmma::mma_sync(acc1, fa, fb1, acc1);
        __syncthreads();
    }
    wmma::store_matrix_sync(sC + mh * 16 * 128 + nq * 32, acc0, 128, wmma::mem_row_major);
    wmma::store_matrix_sync(sC + mh * 16 * 128 + nq * 32 + 16, acc1, 128, wmma::mem_row_major);
    __syncthreads();
    for (int i = threadIdx.x; i < 32 * 128; i += 256) {
        int m = i >> 7, n = i & 127;
        float v = sC[i] + bias[n0 + n];
        if (relu) v = fmaxf(v, 0.f);
        C[(size_t)m * N + n0 + n] = v;
    }
}

// ---------------- LSTM cell updates ----------------
__global__ void cell_enc_kernel(int t) {
    int i = blockIdx.x * blockDim.x + threadIdx.x;
    if (i >= BATCH * HID) return;
    int b = i / HID, d = i % HID;
    const float* g = d_gates + b * G4;
    float ig = sigm(g[d]);
    float fg = sigm(g[d + HID]);
    float gg = tanhf(g[d + 2 * HID]);
    float og = sigm(g[d + 3 * HID]);
    float c = fg * d_ce[i] + ig * gg;
    float h = og * tanhf(c);
    d_ce[i] = c; d_he[i] = h;
    d_enc_outs[(size_t)b * SEQL * HID + (size_t)t * HID + d] = h;
}

__global__ void cell_dec_kernel() {
    int i = blockIdx.x * blockDim.x + threadIdx.x;
    if (i >= BATCH * HID) return;
    int b = i / HID, d = i % HID;
    const float* g = d_gates + b * G4;
    float ig = sigm(g[d]);
    float fg = sigm(g[d + HID]);
    float gg = tanhf(g[d + 2 * HID]);
    float og = sigm(g[d + 3 * HID]);
    float c = fg * d_cd[i] + ig * gg;
    float h = og * tanhf(c);
    d_cd[i] = c; d_hd[i] = h;
}

// ---------------- attention softmax + context ----------------
__global__ void softmax_ctx_kernel() {
    int b = blockIdx.x;
    __shared__ float aw[SEQL];
    if (threadIdx.x == 0) {
        const float* lg = d_alog + b * 128;
        float mx = lg[0];
        for (int l = 1; l < SEQL; l++) mx = fmaxf(mx, lg[l]);
        float s = 0.f;
        for (int l = 0; l < SEQL; l++) { float e = expf(lg[l] - mx); aw[l] = e; s += e; }
        float inv = 1.f / s;
        for (int l = 0; l < SEQL; l++) aw[l] *= inv;
    }
    __syncthreads();
    const float* eo = d_enc_outs + (size_t)b * SEQL * HID;
    for (int d = threadIdx.x; d < HID; d += blockDim.x) {
        float s = 0.f;
        #pragma unroll 4
        for (int l = 0; l < SEQL; l++) s += aw[l] * eo[(size_t)l * HID + d];
        d_ctx[b * HID + d] = s;
    }
}

// ---------------- log_softmax + argmax + output write + next-embedding gather ----------------
__global__ void finalize_kernel(const float* __restrict__ dec_embed, float* __restrict__ out, int step) {
    int b = blockIdx.x;
    int tid = threadIdx.x;
    const float* lg = d_logits + (size_t)b * VOCAB;

    __shared__ float sv[256];
    __shared__ int   si[256];

    // pass 1: max + argmax (first-occurrence tie-break)
    float bm = -INFINITY; int bi = 0;
    for (int v = tid; v < VOCAB; v += 256) {
        float x = lg[v];
        if (x > bm) { bm = x; bi = v; }
    }
    sv[tid] = bm; si[tid] = bi;
    __syncthreads();
    for (int s = 128; s > 0; s >>= 1) {
        if (tid < s) {
            float ov = sv[tid + s]; int oi = si[tid + s];
            if (ov > sv[tid] || (ov == sv[tid] && oi < si[tid])) { sv[tid] = ov; si[tid] = oi; }
        }
        __syncthreads();
    }
    float mx = sv[0];
    int am = si[0];
    __syncthreads();

    // pass 2: sum exp
    float s = 0.f;
    for (int v = tid; v < VOCAB; v += 256) s += expf(lg[v] - mx);
    sv[tid] = s;
    __syncthreads();
    for (int st = 128; st > 0; st >>= 1) {
        if (tid < st) sv[tid] += sv[tid + st];
        __syncthreads();
    }
    float lse = mx + logf(sv[0]);

    // pass 3: write log-softmax to output [b][step][v]
    float* op = out + ((size_t)b * SEQL + step) * VOCAB;
    for (int v = tid; v < VOCAB; v += 256) op[v] = lg[v] - lse;

    // pass 4: gather next decoder embedding for argmax token
    const float* er = dec_embed + (size_t)am * HID;
    for (int d = tid; d < HID; d += 256) d_ebuf[b * HID + d] = er[d];
}

// ---------------- host launch ----------------
extern "C" void kernel_launch(void* const* d_in, const int* in_sizes, int n_in,
                              void* d_out, int out_size) {
    (void)in_sizes; (void)n_in; (void)out_size;
    const int*   x         = (const int*)d_in[0];
    const float* enc_embed = (const float*)d_in[1];
    const float* enc_wx    = (const float*)d_in[2];
    const float* enc_wh    = (const float*)d_in[3];
    const float* enc_b     = (const float*)d_in[4];
    const float* dec_embed = (const float*)d_in[5];
    const float* attn_w    = (const float*)d_in[6];
    const float* attn_b    = (const float*)d_in[7];
    const float* comb_w    = (const float*)d_in[8];
    const float* comb_b    = (const float*)d_in[9];
    const float* dec_wx    = (const float*)d_in[10];
    const float* dec_wh    = (const float*)d_in[11];
    const float* dec_b     = (const float*)d_in[12];
    const float* out_w     = (const float*)d_in[13];
    const float* out_b     = (const float*)d_in[14];
    float* out = (float*)d_out;

    // resolve device-global addresses (host-side, capture-safe)
    float *p_Eenc, *p_he, *p_hd, *p_gates, *p_ebuf, *p_ctx, *p_inp, *p_alog, *p_abias, *p_logits;
    __nv_bfloat16 *p_Wenc, *p_Wdec, *p_Wcomb, *p_Wout, *p_Wattn;
    cudaGetSymbolAddress((void**)&p_Eenc,  d_Eenc);
    cudaGetSymbolAddress((void**)&p_he,    d_he);
    cudaGetSymbolAddress((void**)&p_hd,    d_hd);
    cudaGetSymbolAddress((void**)&p_gates, d_gates);
    cudaGetSymbolAddress((void**)&p_ebuf,  d_ebuf);
    cudaGetSymbolAddress((void**)&p_ctx,   d_ctx);
    cudaGetSymbolAddress((void**)&p_inp,   d_inp);
    cudaGetSymbolAddress((void**)&p_alog,  d_alog);
    cudaGetSymbolAddress((void**)&p_abias, d_abias);
    cudaGetSymbolAddress((void**)&p_logits, d_logits);
    cudaGetSymbolAddress((void**)&p_Wenc,  d_Wenc);
    cudaGetSymbolAddress((void**)&p_Wdec,  d_Wdec);
    cudaGetSymbolAddress((void**)&p_Wcomb, d_Wcomb);
    cudaGetSymbolAddress((void**)&p_Wout,  d_Wout);
    cudaGetSymbolAddress((void**)&p_Wattn, d_Wattn);

    // ---- setup: convert weights to bf16, gather embeddings, init state ----
    cvt_kernel<<<2048, 256>>>(enc_wx, p_Wenc,                      (size_t)EMBED * G4);
    cvt_kernel<<<2048, 256>>>(enc_wh, p_Wenc + (size_t)EMBED * G4, (size_t)HID * G4);
    cvt_kernel<<<2048, 256>>>(dec_wx, p_Wdec,                      (size_t)HID * G4);
    cvt_kernel<<<2048, 256>>>(dec_wh, p_Wdec + (size_t)HID * G4,   (size_t)HID * G4);
    cvt_kernel<<<2048, 256>>>(comb_w, p_Wcomb,                     (size_t)2 * HID * HID);
    cvt_kernel<<<4096, 256>>>(out_w,  p_Wout,                      (size_t)HID * VOCAB);
    cvt_pad_attn_kernel<<<1024, 256>>>(attn_w);
    init_state_kernel<<<(BATCH * HID + 255) / 256, 256>>>(attn_b, dec_embed);
    gather_enc_kernel<<<2048, 256>>>(x, enc_embed);

    // ---- encoder: 64 sequential steps ----
    for (int t = 0; t < SEQL; t++) {
        gemm32_kernel<<<G4 / 128, 256>>>(p_Eenc + (size_t)t * BATCH * EMBED, EMBED,
                                         p_he, HID, p_Wenc, G4, enc_b, p_gates, 0);
        cell_enc_kernel<<<(BATCH * HID + 255) / 256, 256>>>(t);
    }

    // ---- decoder: 64 sequential steps with greedy feedback ----
    for (int s = 0; s < SEQL; s++) {
        // attention logits: [e|h] @ attn_w (padded to N=128)
        gemm32_kernel<<<1, 256>>>(p_ebuf, HID, p_hd, HID, p_Wattn, 128, p_abias, p_alog, 0);
        softmax_ctx_kernel<<<BATCH, 256>>>();
        // combine: relu([e|ctx] @ comb_w + b)
        gemm32_kernel<<<HID / 128, 256>>>(p_ebuf, HID, p_ctx, HID, p_Wcomb, HID, comb_b, p_inp, 1);
        // LSTM gates: [inp|h] @ [dec_wx; dec_wh] + b
        gemm32_kernel<<<G4 / 128, 256>>>(p_inp, HID, p_hd, HID, p_Wdec, G4, dec_b, p_gates, 0);
        cell_dec_kernel<<<(BATCH * HID + 255) / 256, 256>>>();
        // output projection: h @ out_w + out_b
        gemm32_kernel<<<VOCAB / 128, 256>>>(p_hd, HID, (const float*)nullptr, 0,
                                            p_Wout, VOCAB, out_b, p_logits, 0);
        finalize_kernel<<<BATCH, 256>>>(dec_embed, out, s);
    }
}

// round 4
// speedup vs baseline: 1.6745x; 1.6745x over previous
#include <cuda_runtime.h>
#include <cuda_bf16.h>
#include <mma.h>
#include <math.h>

using namespace nvcuda;

#define VOCAB 32000
#define EMBED 512
#define HID   1024      // DEC_H
#define SEQL  64
#define BATCH 32
#define G4    4096      // 4*HID
#define KCHUNK 128

// ---------------- device scratch (static: no allocs allowed) ----------------
__device__ float d_Eenc[SEQL * BATCH * EMBED];        // gathered encoder embeddings [t][b][e]
__device__ float d_enc_outs[BATCH * SEQL * HID];      // [b][t][d]
__device__ float d_he[BATCH * HID], d_ce[BATCH * HID];
__device__ float d_hd[BATCH * HID], d_cd[BATCH * HID];
__device__ float d_ebuf[BATCH * HID];
__device__ float d_ctx[BATCH * HID];
__device__ float d_inp[BATCH * HID];
__device__ float d_logits[(size_t)BATCH * VOCAB];
__device__ float d_benc[G4], d_bdec[G4];              // interleaved biases (col = 4*d+g)

__device__ __nv_bfloat16 d_Wenc[(EMBED + HID) * G4];  // [enc_wx; enc_wh], cols interleaved 4*d+g
__device__ __nv_bfloat16 d_Wdec[(2 * HID) * G4];      // [dec_wx; dec_wh], cols interleaved
__device__ __nv_bfloat16 d_Wcomb[(2 * HID) * HID];
__device__ __nv_bfloat16 d_Wout[(size_t)HID * VOCAB];

__device__ __forceinline__ float sigm(float x) { return 1.f / (1.f + expf(-x)); }

// ---------------- weight prep ----------------
__global__ void cvt_kernel(const float* __restrict__ src, __nv_bfloat16* __restrict__ dst, size_t n) {
    for (size_t i = (size_t)blockIdx.x * blockDim.x + threadIdx.x; i < n;
         i += (size_t)gridDim.x * blockDim.x)
        dst[i] = __float2bfloat16(src[i]);
}

// interleave gate columns: dst[k][4*d+g] = srcX/srcH[k][g*HID+d]; also bias
__global__ void interleave_kernel(const float* __restrict__ wx, int K1,
                                  const float* __restrict__ wh,
                                  const float* __restrict__ b,
                                  __nv_bfloat16* __restrict__ dst,
                                  float* __restrict__ bdst, int Ktot) {
    size_t n = (size_t)Ktot * G4;
    for (size_t i = (size_t)blockIdx.x * blockDim.x + threadIdx.x; i < n;
         i += (size_t)gridDim.x * blockDim.x) {
        int k = (int)(i >> 12), c = (int)(i & 4095);
        int d = c >> 2, g = c & 3;
        int sc = g * HID + d;
        float v = (k < K1) ? wx[(size_t)k * G4 + sc] : wh[(size_t)(k - K1) * G4 + sc];
        dst[i] = __float2bfloat16(v);
        if (k == 0) bdst[c] = b[sc];
    }
}

__global__ void init_state_kernel(const float* __restrict__ dec_embed) {
    int i = blockIdx.x * blockDim.x + threadIdx.x;
    if (i < BATCH * HID) {
        d_he[i] = 0.f; d_ce[i] = 0.f; d_hd[i] = 0.f; d_cd[i] = 0.f;
        d_ebuf[i] = dec_embed[(size_t)127 * HID + (i % HID)];
    }
}

__global__ void gather_enc_kernel(const int* __restrict__ x, const float* __restrict__ enc_embed) {
    size_t n = (size_t)SEQL * BATCH * EMBED;
    for (size_t i = (size_t)blockIdx.x * blockDim.x + threadIdx.x; i < n;
         i += (size_t)gridDim.x * blockDim.x) {
        int t = (int)(i / (BATCH * EMBED));
        int r = (int)(i % (BATCH * EMBED));
        int b = r / EMBED, d = r % EMBED;
        int tok = x[b * SEQL + t];
        d_Eenc[i] = enc_embed[(size_t)tok * EMBED + d];
    }
}

// ---------------- GEMM: C[32][N] = [A1|A2](fp32->bf16) @ B(bf16) ----------------
// MODE 0: C = acc + bias          (out projection)
// MODE 1: C = relu(acc + bias)    (combine)
// MODE 2: encoder LSTM cell epilogue (interleaved gates), writes d_he/d_ce/d_enc_outs[t]
// MODE 3: decoder LSTM cell epilogue, writes d_hd/d_cd
template<int MODE>
__global__ __launch_bounds__(256) void gemm32k(
    const float* __restrict__ A1, int K1,
    const float* __restrict__ A2, int K2,
    const __nv_bfloat16* __restrict__ Bw, int N,
    const float* __restrict__ bias,
    float* __restrict__ C, int t)
{
    __shared__ __align__(16) __nv_bfloat16 sA[32 * KCHUNK];
    __shared__ float sC[32 * 128];

    const int n0 = blockIdx.x * 128;
    const int tid = threadIdx.x;
    const int w = tid >> 5;
    const int mh = w >> 2, nq = w & 3;

    wmma::fragment<wmma::matrix_a, 16, 16, 16, __nv_bfloat16, wmma::row_major> fa;
    wmma::fragment<wmma::matrix_b, 16, 16, 16, __nv_bfloat16, wmma::row_major> fb0, fb1;
    wmma::fragment<wmma::accumulator, 16, 16, 16, float> acc0, acc1;
    wmma::fill_fragment(acc0, 0.f);
    wmma::fill_fragment(acc1, 0.f);

    const int K = K1 + K2;
    for (int k0 = 0; k0 < K; k0 += KCHUNK) {
        // stage A chunk 32 x 128 fp32 -> bf16 (vectorized float4, 4 per thread)
        // chunk never straddles the K1/K2 split (all K1 are multiples of KCHUNK)
        const float* src; int ldk;
        if (k0 < K1) { src = A1 + k0; ldk = K1; }
        else         { src = A2 + (k0 - K1); ldk = K2; }
        #pragma unroll
        for (int r = 0; r < 4; r++) {
            int i = tid + r * 256;            // 1024 float4 slots
            int m = i >> 5, kq = i & 31;
            float4 f = ((const float4*)(src + (size_t)m * ldk))[kq];
            __nv_bfloat162 lo = __floats2bfloat162_rn(f.x, f.y);
            __nv_bfloat162 hi = __floats2bfloat162_rn(f.z, f.w);
            uint2 u;
            u.x = *(unsigned int*)&lo;
            u.y = *(unsigned int*)&hi;
            ((uint2*)(sA + m * KCHUNK))[kq] = u;
        }
        __syncthreads();
        #pragma unroll
        for (int kk = 0; kk < KCHUNK / 16; kk++) {
            wmma::load_matrix_sync(fa, sA + mh * 16 * KCHUNK + kk * 16, KCHUNK);
            const __nv_bfloat16* bp = Bw + (size_t)(k0 + kk * 16) * N + n0 + nq * 32;
            wmma::load_matrix_sync(fb0, bp, N);
            wmma::load_matrix_sync(fb1, bp + 16, N);
            wmma::mma_sync(acc0, fa, fb0, acc0);
            wmma::mma_sync(acc1, fa, fb1, acc1);
        }
        __syncthreads();
    }
    wmma::store_matrix_sync(sC + mh * 16 * 128 + nq * 32, acc0, 128, wmma::mem_row_major);
    wmma::store_matrix_sync(sC + mh * 16 * 128 + nq * 32 + 16, acc1, 128, wmma::mem_row_major);
    __syncthreads();

    if (MODE <= 1) {
        for (int i = tid; i < 32 * 128; i += 256) {
            int m = i >> 7, n = i & 127;
            float v = sC[i] + bias[n0 + n];
            if (MODE == 1) v = fmaxf(v, 0.f);
            C[(size_t)m * N + n0 + n] = v;
        }
    } else {
        // interleaved gates: local col = 4*dd+g, global d = n0/4 + dd
        for (int i = tid; i < 32 * 32; i += 256) {
            int m = i >> 5, dd = i & 31;
            int cb = dd * 4;
            float gi = sigm(sC[m * 128 + cb + 0] + bias[n0 + cb + 0]);
            float gf = sigm(sC[m * 128 + cb + 1] + bias[n0 + cb + 1]);
            float gg = tanhf(sC[m * 128 + cb + 2] + bias[n0 + cb + 2]);
            float go = sigm(sC[m * 128 + cb + 3] + bias[n0 + cb + 3]);
            int d = (n0 >> 2) + dd;
            int idx = m * HID + d;
            if (MODE == 2) {
                float c = gf * d_ce[idx] + gi * gg;
                float h = go * tanhf(c);
                d_ce[idx] = c; d_he[idx] = h;
                d_enc_outs[(size_t)m * SEQL * HID + (size_t)t * HID + d] = h;
            } else {
                float c = gf * d_cd[idx] + gi * gg;
                float h = go * tanhf(c);
                d_cd[idx] = c; d_hd[idx] = h;
            }
        }
    }
}

// ---------------- fused attention: logits + softmax + context ----------------
__global__ __launch_bounds__(256) void attn_ctx_kernel(const float* __restrict__ attn_w,
                                                       const float* __restrict__ attn_b) {
    int b = blockIdx.x;
    int tid = threadIdx.x;
    __shared__ float red[256];
    __shared__ float aw[SEQL];

    // logits: [e|h] @ attn_w ([2048][64] row-major) ; thread (q,l): q=tid>>6, l=tid&63
    int l = tid & 63, q = tid >> 6;
    const float* e = d_ebuf + b * HID;
    const float* h = d_hd + b * HID;
    float part = 0.f;
    for (int k = q * 512; k < q * 512 + 512; k++) {
        float a = (k < HID) ? e[k] : h[k - HID];
        part += a * attn_w[(size_t)k * SEQL + l];
    }
    red[tid] = part;
    __syncthreads();
    if (tid == 0) {
        float mx = -INFINITY;
        float lg[SEQL];
        for (int j = 0; j < SEQL; j++) {
            float v = red[j] + red[64 + j] + red[128 + j] + red[192 + j] + attn_b[j];
            lg[j] = v; mx = fmaxf(mx, v);
        }
        float s = 0.f;
        for (int j = 0; j < SEQL; j++) { float ev = expf(lg[j] - mx); aw[j] = ev; s += ev; }
        float inv = 1.f / s;
        for (int j = 0; j < SEQL; j++) aw[j] *= inv;
    }
    __syncthreads();
    // context: ctx[d] = sum_l aw[l] * enc_outs[b][l][d]
    const float* eo = d_enc_outs + (size_t)b * SEQL * HID;
    #pragma unroll
    for (int r = 0; r < HID / 256; r++) {
        int d = tid + r * 256;
        float s = 0.f;
        #pragma unroll 8
        for (int ll = 0; ll < SEQL; ll++) s += aw[ll] * eo[(size_t)ll * HID + d];
        d_ctx[b * HID + d] = s;
    }
}

// ---------------- log_softmax + argmax + output + next-embedding gather ----------------
__global__ __launch_bounds__(256) void finalize_kernel(const float* __restrict__ dec_embed,
                                                       float* __restrict__ out, int step) {
    int b = blockIdx.x;
    int tid = threadIdx.x;
    const float* lg = d_logits + (size_t)b * VOCAB;

    __shared__ float sv[256];
    __shared__ int   si[256];

    float bm = -INFINITY; int bi = 0;
    for (int v = tid; v < VOCAB; v += 256) {
        float x = lg[v];
        if (x > bm) { bm = x; bi = v; }
    }
    sv[tid] = bm; si[tid] = bi;
    __syncthreads();
    for (int s = 128; s > 0; s >>= 1) {
        if (tid < s) {
            float ov = sv[tid + s]; int oi = si[tid + s];
            if (ov > sv[tid] || (ov == sv[tid] && oi < si[tid])) { sv[tid] = ov; si[tid] = oi; }
        }
        __syncthreads();
    }
    float mx = sv[0];
    int am = si[0];
    __syncthreads();

    float s = 0.f;
    for (int v = tid; v < VOCAB; v += 256) s += expf(lg[v] - mx);
    sv[tid] = s;
    __syncthreads();
    for (int st = 128; st > 0; st >>= 1) {
        if (tid < st) sv[tid] += sv[tid + st];
        __syncthreads();
    }
    float lse = mx + logf(sv[0]);

    float* op = out + ((size_t)b * SEQL + step) * VOCAB;
    for (int v = tid; v < VOCAB; v += 256) op[v] = lg[v] - lse;

    const float* er = dec_embed + (size_t)am * HID;
    for (int d = tid; d < HID; d += 256) d_ebuf[b * HID + d] = er[d];
}

// ---------------- host launch ----------------
extern "C" void kernel_launch(void* const* d_in, const int* in_sizes, int n_in,
                              void* d_out, int out_size) {
    (void)in_sizes; (void)n_in; (void)out_size;
    const int*   x         = (const int*)d_in[0];
    const float* enc_embed = (const float*)d_in[1];
    const float* enc_wx    = (const float*)d_in[2];
    const float* enc_wh    = (const float*)d_in[3];
    const float* enc_b     = (const float*)d_in[4];
    const float* dec_embed = (const float*)d_in[5];
    const float* attn_w    = (const float*)d_in[6];
    const float* attn_b    = (const float*)d_in[7];
    const float* comb_w    = (const float*)d_in[8];
    const float* comb_b    = (const float*)d_in[9];
    const float* dec_wx    = (const float*)d_in[10];
    const float* dec_wh    = (const float*)d_in[11];
    const float* dec_b     = (const float*)d_in[12];
    const float* out_w     = (const float*)d_in[13];
    const float* out_b     = (const float*)d_in[14];
    float* out = (float*)d_out;

    float *p_Eenc, *p_he, *p_hd, *p_ebuf, *p_ctx, *p_inp, *p_logits, *p_benc, *p_bdec;
    __nv_bfloat16 *p_Wenc, *p_Wdec, *p_Wcomb, *p_Wout;
    cudaGetSymbolAddress((void**)&p_Eenc,   d_Eenc);
    cudaGetSymbolAddress((void**)&p_he,     d_he);
    cudaGetSymbolAddress((void**)&p_hd,     d_hd);
    cudaGetSymbolAddress((void**)&p_ebuf,   d_ebuf);
    cudaGetSymbolAddress((void**)&p_ctx,    d_ctx);
    cudaGetSymbolAddress((void**)&p_inp,    d_inp);
    cudaGetSymbolAddress((void**)&p_logits, d_logits);
    cudaGetSymbolAddress((void**)&p_benc,   d_benc);
    cudaGetSymbolAddress((void**)&p_bdec,   d_bdec);
    cudaGetSymbolAddress((void**)&p_Wenc,   d_Wenc);
    cudaGetSymbolAddress((void**)&p_Wdec,   d_Wdec);
    cudaGetSymbolAddress((void**)&p_Wcomb,  d_Wcomb);
    cudaGetSymbolAddress((void**)&p_Wout,   d_Wout);

    // ---- setup ----
    interleave_kernel<<<2048, 256>>>(enc_wx, EMBED, enc_wh, enc_b, p_Wenc, p_benc, EMBED + HID);
    interleave_kernel<<<2048, 256>>>(dec_wx, HID,   dec_wh, dec_b, p_Wdec, p_bdec, 2 * HID);
    cvt_kernel<<<2048, 256>>>(comb_w, p_Wcomb, (size_t)2 * HID * HID);
    cvt_kernel<<<4096, 256>>>(out_w,  p_Wout,  (size_t)HID * VOCAB);
    init_state_kernel<<<(BATCH * HID + 255) / 256, 256>>>(dec_embed);
    gather_enc_kernel<<<2048, 256>>>(x, enc_embed);

    // ---- encoder: 64 sequential steps (fused GEMM + cell) ----
    for (int t = 0; t < SEQL; t++) {
        gemm32k<2><<<G4 / 128, 256>>>(p_Eenc + (size_t)t * BATCH * EMBED, EMBED,
                                      p_he, HID, p_Wenc, G4, p_benc, nullptr, t);
    }

    // ---- decoder: 64 sequential steps ----
    for (int s = 0; s < SEQL; s++) {
        attn_ctx_kernel<<<BATCH, 256>>>(attn_w, attn_b);
        gemm32k<1><<<HID / 128, 256>>>(p_ebuf, HID, p_ctx, HID, p_Wcomb, HID, comb_b, p_inp, 0);
        gemm32k<3><<<G4 / 128, 256>>>(p_inp, HID, p_hd, HID, p_Wdec, G4, p_bdec, nullptr, 0);
        gemm32k<0><<<VOCAB / 128, 256>>>(p_hd, HID, (const float*)nullptr, 0,
                                         p_Wout, VOCAB, out_b, p_logits, 0);
        finalize_kernel<<<BATCH, 256>>>(dec_embed, out, s);
    }
}

// round 8
// speedup vs baseline: 3.2486x; 1.9401x over previous
#include <cuda_runtime.h>
#include <cuda_bf16.h>
#include <mma.h>
#include <math.h>

using namespace nvcuda;

#define VOCAB 32000
#define EMBED 512
#define HID   1024      // DEC_H
#define SEQL  64
#define BATCH 32
#define G4    4096
#define GRID  148
#define TPB   256
#define PAD   8

#define T_ENC 64        // G4/64 tiles
#define T_DEC 64
#define T_CMB 16        // HID/64
#define T_OUT 500       // VOCAB/64

#define SMEM_DYN (32*(2*HID+PAD)*2 + 32*64*4)   // 131584 + 8192 = 139776

// ---------------- device scratch ----------------
__device__ float d_Eenc[SEQL * BATCH * EMBED];
__device__ float d_enc_outs[BATCH * SEQL * HID];
__device__ float d_g0[BATCH * HID], d_g1[BATCH * HID], d_ce[BATCH * HID];   // encoder h ping-pong + c
__device__ float d_h0[BATCH * HID], d_h1[BATCH * HID], d_cd[BATCH * HID];   // decoder h ping-pong + c
__device__ float d_ebuf[BATCH * HID];
__device__ float d_ctx[BATCH * HID];
__device__ float d_inp[BATCH * HID];
__device__ float d_logits[(size_t)BATCH * VOCAB];
__device__ float d_benc[G4], d_bdec[G4];
__device__ float d_pm[BATCH * 512], d_ps[BATCH * 512];
__device__ int   d_pa[BATCH * 512];
__device__ float d_lse[BATCH];
__device__ unsigned g_bar;       // full-grid barrier counter
__device__ unsigned g_bar_enc;   // 64-block encoder barrier counter

__device__ __nv_bfloat16 d_Wenc[(size_t)T_ENC * (EMBED + HID) * 64];  // [tile][k][64], gate-interleaved cols
__device__ __nv_bfloat16 d_Wdec[(size_t)T_DEC * (2 * HID) * 64];
__device__ __nv_bfloat16 d_Wcmb[(size_t)T_CMB * (2 * HID) * 64];
__device__ __nv_bfloat16 d_Wout[(size_t)T_OUT * HID * 64];

__device__ __forceinline__ float sigm(float x) { return 1.f / (1.f + expf(-x)); }

// ---------------- software barriers (all participating blocks co-resident) ----------------
__device__ __forceinline__ void sw_barrier(unsigned* ctr, unsigned& gen, unsigned nblk) {
    __threadfence();                       // release: order my writes to L2
    __syncthreads();
    if (threadIdx.x == 0) {
        unsigned target = (gen + 1u) * nblk;
        atomicAdd(ctr, 1u);
        while (*((volatile unsigned*)ctr) < target) __nanosleep(64);
        __threadfence();                   // acquire: CCTL.IVALL -> invalidate SM's L1D
    }
    gen++;
    __syncthreads();                       // post-barrier loads happen after the IVALL
}

// ---------------- A staging: 32 x (K1+K2) fp32 -> bf16 smem, ldm = K+PAD ----------------
template<int K1, int K2>
__device__ __forceinline__ void stage_A(__nv_bfloat16* sA, const float* __restrict__ A1,
                                        const float* __restrict__ A2) {
    constexpr int K = K1 + K2;
    constexpr int tot = 32 * K / 4;
    for (int i = threadIdx.x; i < tot; i += TPB) {
        int m = i / (K / 4);
        int k = (i - m * (K / 4)) * 4;
        const float* s = (K2 == 0 || k < K1) ? (A1 + m * K1 + k) : (A2 + m * K2 + (k - K1));
        float4 f = *(const float4*)s;
        __nv_bfloat162 lo = __floats2bfloat162_rn(f.x, f.y);
        __nv_bfloat162 hi = __floats2bfloat162_rn(f.z, f.w);
        uint2 u; u.x = *(unsigned*)&lo; u.y = *(unsigned*)&hi;
        *(uint2*)(sA + m * (K + PAD) + k) = u;
    }
    __syncthreads();
}

// ---------------- GEMM tile: sC[32][64] = sA[32][K] @ Bt[K][64] ----------------
template<int K>
__device__ __forceinline__ void gemm_tile(const __nv_bfloat16* sA,
                                          const __nv_bfloat16* __restrict__ Bt,
                                          float* sC) {
    constexpr int LDA = K + PAD;
    const int w = threadIdx.x >> 5;
    const int mh = w >> 2, nq = w & 3;
    wmma::fragment<wmma::matrix_a, 16, 16, 16, __nv_bfloat16, wmma::row_major> fa;
    wmma::fragment<wmma::matrix_b, 16, 16, 16, __nv_bfloat16, wmma::row_major> fb;
    wmma::fragment<wmma::accumulator, 16, 16, 16, float> acc, acc2;
    wmma::fill_fragment(acc, 0.f);
    wmma::fill_fragment(acc2, 0.f);
    #pragma unroll 4
    for (int k = 0; k < K; k += 32) {
        wmma::load_matrix_sync(fa, sA + mh * 16 * LDA + k, LDA);
        wmma::load_matrix_sync(fb, Bt + (size_t)k * 64 + nq * 16, 64);
        wmma::mma_sync(acc, fa, fb, acc);
        wmma::load_matrix_sync(fa, sA + mh * 16 * LDA + k + 16, LDA);
        wmma::load_matrix_sync(fb, Bt + (size_t)(k + 16) * 64 + nq * 16, 64);
        wmma::mma_sync(acc2, fa, fb, acc2);
    }
    #pragma unroll
    for (int i = 0; i < acc.num_elements; i++) acc.x[i] += acc2.x[i];
    wmma::store_matrix_sync(sC + mh * 16 * 64 + nq * 16, acc, 64, wmma::mem_row_major);
    __syncthreads();
}

// ---------------- LSTM cell epilogue (interleaved gates, tile n0) ----------------
__device__ __forceinline__ void cell_epi(const float* sC, const float* bias, int n0,
                                         float* cbuf, float* hnew_base, float* enc_out, int t) {
    for (int i = threadIdx.x; i < BATCH * 16; i += TPB) {
        int m = i >> 4, dd = i & 15, cb = dd * 4;
        float gi = sigm(sC[m * 64 + cb + 0] + bias[n0 + cb + 0]);
        float gf = sigm(sC[m * 64 + cb + 1] + bias[n0 + cb + 1]);
        float gg = tanhf(sC[m * 64 + cb + 2] + bias[n0 + cb + 2]);
        float go = sigm(sC[m * 64 + cb + 3] + bias[n0 + cb + 3]);
        int d = (n0 >> 2) + dd;
        int idx = m * HID + d;
        float c = gf * cbuf[idx] + gi * gg;
        float h = go * tanhf(c);
        cbuf[idx] = c;
        hnew_base[idx] = h;
        if (enc_out) enc_out[((size_t)m * SEQL + t) * HID + d] = h;
    }
    __syncthreads();
}

// ---------------- out-projection epilogue: logits + online-softmax partials ----------------
__device__ __forceinline__ void epi_out(const float* sC, const float* __restrict__ out_b, int tile) {
    const int tid = threadIdx.x;
    const int r = tid >> 3, c0 = (tid & 7) * 8, n0 = tile * 64;
    float v[8];
    float pm = -INFINITY; int pa = 0;
    #pragma unroll
    for (int j = 0; j < 8; j++) {
        float x = sC[r * 64 + c0 + j] + out_b[n0 + c0 + j];
        v[j] = x;
        if (x > pm) { pm = x; pa = n0 + c0 + j; }
    }
    float4* dst = (float4*)(d_logits + (size_t)r * VOCAB + n0 + c0);
    dst[0] = make_float4(v[0], v[1], v[2], v[3]);
    dst[1] = make_float4(v[4], v[5], v[6], v[7]);
    float ps = 0.f;
    #pragma unroll
    for (int j = 0; j < 8; j++) ps += expf(v[j] - pm);
    // xor-shuffle merge within each 8-lane group (one batch row)
    #pragma unroll
    for (int o = 4; o > 0; o >>= 1) {
        float om = __shfl_xor_sync(0xffffffffu, pm, o);
        float os = __shfl_xor_sync(0xffffffffu, ps, o);
        int   oa = __shfl_xor_sync(0xffffffffu, pa, o);
        if (om > pm) { ps = ps * expf(pm - om) + os; pm = om; pa = oa; }
        else if (om == pm) { ps += os; if (oa < pa) pa = oa; }
        else ps += os * expf(om - pm);
    }
    if ((tid & 7) == 0) {
        d_pm[r * 512 + tile] = pm;
        d_ps[r * 512 + tile] = ps;
        d_pa[r * 512 + tile] = pa;
    }
    __syncthreads();
}

// ---------------- attention: logits + softmax + context for batch b ----------------
__device__ void attn_phase(int b, const float* __restrict__ attn_w,
                           const float* __restrict__ attn_b, const float* hr, float* scratch) {
    float* red = scratch;          // 256
    float* aw  = scratch + 256;    // 64
    const int tid = threadIdx.x;
    const int l = tid & 63, q = tid >> 6;
    const float* e = d_ebuf + b * HID;
    const float* h = hr + b * HID;
    float part = 0.f;
    for (int k = q * 512; k < q * 512 + 512; k++) {
        float a = (k < HID) ? e[k] : h[k - HID];
        part += a * attn_w[(size_t)k * SEQL + l];
    }
    red[tid] = part;
    __syncthreads();
    if (tid < 64)
        aw[tid] = red[tid] + red[64 + tid] + red[128 + tid] + red[192 + tid] + attn_b[tid];
    __syncthreads();
    if (tid == 0) {
        float mx = -INFINITY;
        for (int j = 0; j < SEQL; j++) mx = fmaxf(mx, aw[j]);
        float s = 0.f;
        for (int j = 0; j < SEQL; j++) { float ev = expf(aw[j] - mx); aw[j] = ev; s += ev; }
        float inv = 1.f / s;
        for (int j = 0; j < SEQL; j++) aw[j] *= inv;
    }
    __syncthreads();
    const float* eo = d_enc_outs + (size_t)b * SEQL * HID;
    #pragma unroll
    for (int r = 0; r < HID / TPB; r++) {
        int d = tid + r * TPB;
        float s = 0.f;
        #pragma unroll 8
        for (int ll = 0; ll < SEQL; ll++) s += aw[ll] * eo[(size_t)ll * HID + d];
        d_ctx[b * HID + d] = s;
    }
    __syncthreads();
}

// ---------------- reduce partials -> lse, argmax token, gather next embedding ----------------
__device__ void reduce_phase(int b, const float* __restrict__ dec_embed, float* scratch) {
    const int tid = threadIdx.x;
    float* smax = scratch;
    float* ssum = scratch + 256;
    int*   sarg = (int*)(scratch + 512);
    int*   stok = (int*)(scratch + 768);
    float pm = -INFINITY, ps = 0.f; int pa = 0;
    for (int t = tid; t < T_OUT; t += TPB) {
        float om = d_pm[b * 512 + t], os = d_ps[b * 512 + t];
        int oa = d_pa[b * 512 + t];
        if (om > pm) { ps = ps * expf(pm - om) + os; pm = om; pa = oa; }
        else if (om == pm) { ps += os; if (oa < pa) pa = oa; }
        else ps += os * expf(om - pm);
    }
    smax[tid] = pm; ssum[tid] = ps; sarg[tid] = pa;
    __syncthreads();
    for (int st = 128; st > 0; st >>= 1) {
        if (tid < st) {
            float om = smax[tid + st], os = ssum[tid + st]; int oa = sarg[tid + st];
            float cm = smax[tid],      cs = ssum[tid];      int ca = sarg[tid];
            if (om > cm) { cs = cs * expf(cm - om) + os; cm = om; ca = oa; }
            else if (om == cm) { cs += os; if (oa < ca) ca = oa; }
            else cs += os * expf(om - cm);
            smax[tid] = cm; ssum[tid] = cs; sarg[tid] = ca;
        }
        __syncthreads();
    }
    if (tid == 0) { d_lse[b] = smax[0] + logf(ssum[0]); stok[0] = sarg[0]; }
    __syncthreads();
    int token = stok[0];
    for (int d = tid; d < HID; d += TPB)
        d_ebuf[b * HID + d] = dec_embed[(size_t)token * HID + d];
    __syncthreads();
}

// ---------------- distributed log-p write: out[b][step][:] = d_logits[b] - lse[b] ----------------
__device__ void fixup_logp(int step, float* __restrict__ out, int bfirst, int nblocks) {
    int lb = blockIdx.x - bfirst;
    const int tot = BATCH * (VOCAB / 4);
    for (int i = lb * TPB + threadIdx.x; i < tot; i += nblocks * TPB) {
        int b = i / (VOCAB / 4);
        int q = i - b * (VOCAB / 4);
        float4 f = ((const float4*)(d_logits + (size_t)b * VOCAB))[q];
        float lse = d_lse[b];
        f.x -= lse; f.y -= lse; f.z -= lse; f.w -= lse;
        ((float4*)(out + ((size_t)b * SEQL + step) * VOCAB))[q] = f;
    }
}

// ---------------- persistent kernel: whole encoder + decoder ----------------
__global__ __launch_bounds__(TPB, 1) void seq_kernel(
    const float* __restrict__ attn_w, const float* __restrict__ attn_b,
    const float* __restrict__ comb_b, const float* __restrict__ out_b,
    const float* __restrict__ dec_embed, float* __restrict__ out)
{
    extern __shared__ unsigned char dynmem[];
    __nv_bfloat16* sA = (__nv_bfloat16*)dynmem;
    float* sC = (float*)(dynmem + 32 * (2 * HID + PAD) * 2);
    float* scratch = (float*)sA;
    unsigned gen = 0, gen_enc = 0;
    const int bid = blockIdx.x;

    // ---- encoder: only blocks 0-63 participate; sub-barrier of 64 ----
    if (bid < T_ENC) {
        for (int t = 0; t < SEQL; t++) {
            const float* hr = (t & 1) ? d_g1 : d_g0;
            float*       hw = (t & 1) ? d_g0 : d_g1;
            stage_A<EMBED, HID>(sA, d_Eenc + (size_t)t * BATCH * EMBED, hr);
            gemm_tile<EMBED + HID>(sA, d_Wenc + (size_t)bid * (EMBED + HID) * 64, sC);
            cell_epi(sC, d_benc, bid * 64, d_ce, hw, d_enc_outs, t);
            sw_barrier(&g_bar_enc, gen_enc, T_ENC);
        }
    }
    sw_barrier(&g_bar, gen, GRID);   // everyone: encoder done

    // ---- decoder: 4 phases per step ----
    for (int s = 0; s < SEQL; s++) {
        const float* hr = (s & 1) ? d_h1 : d_h0;   // h from prev step
        float*       hw = (s & 1) ? d_h0 : d_h1;   // h written this step
        // phase EA: reduce(s-1) + attention(s) on blocks 0-31
        if (bid < BATCH) {
            if (s > 0) reduce_phase(bid, dec_embed, scratch);
            attn_phase(bid, attn_w, attn_b, hr, scratch);
        }
        sw_barrier(&g_bar, gen, GRID);
        // phase B: combine (blocks 0-15) || write logp of step s-1 (blocks 16-147)
        if (bid < T_CMB) {
            stage_A<HID, HID>(sA, d_ebuf, d_ctx);
            gemm_tile<2 * HID>(sA, d_Wcmb + (size_t)bid * (2 * HID) * 64, sC);
            int n0 = bid * 64;
            for (int i = threadIdx.x; i < BATCH * 64; i += TPB) {
                int m = i >> 6, j = i & 63;
                float v = sC[m * 64 + j] + comb_b[n0 + j];
                d_inp[m * HID + n0 + j] = fmaxf(v, 0.f);
            }
            __syncthreads();
        } else if (s > 0) {
            fixup_logp(s - 1, out, T_CMB, GRID - T_CMB);
        }
        sw_barrier(&g_bar, gen, GRID);
        // phase C: decoder LSTM gates + cell
        if (bid < T_DEC) {
            stage_A<HID, HID>(sA, d_inp, hr);
            gemm_tile<2 * HID>(sA, d_Wdec + (size_t)bid * (2 * HID) * 64, sC);
            cell_epi(sC, d_bdec, bid * 64, d_cd, hw, nullptr, 0);
        }
        sw_barrier(&g_bar, gen, GRID);
        // phase D: out projection (all blocks)
        stage_A<HID, 0>(sA, hw, nullptr);
        for (int tile = bid; tile < T_OUT; tile += GRID) {
            gemm_tile<HID>(sA, d_Wout + (size_t)tile * HID * 64, sC);
            epi_out(sC, out_b, tile);
        }
        sw_barrier(&g_bar, gen, GRID);
    }
    // tail: reduce + logp write for final step
    if (bid < BATCH) reduce_phase(bid, dec_embed, scratch);
    sw_barrier(&g_bar, gen, GRID);
    fixup_logp(SEQL - 1, out, 0, GRID);
}

// ---------------- prep: convert/retile weights, gather, init (one kernel) ----------------
__global__ void prep_kernel(
    const int* __restrict__ x, const float* __restrict__ enc_embed,
    const float* __restrict__ enc_wx, const float* __restrict__ enc_wh,
    const float* __restrict__ enc_b, const float* __restrict__ dec_embed,
    const float* __restrict__ comb_w,
    const float* __restrict__ dec_wx, const float* __restrict__ dec_wh,
    const float* __restrict__ dec_b, const float* __restrict__ out_w)
{
    const size_t gs = (size_t)gridDim.x * blockDim.x;
    const size_t g0 = (size_t)blockIdx.x * blockDim.x + threadIdx.x;

    // Wenc: tiled + gate-interleaved
    for (size_t i = g0; i < (size_t)T_ENC * 1536 * 64; i += gs) {
        int tile = (int)(i / 98304); int r = (int)(i % 98304);
        int k = r >> 6, j = r & 63;
        int c = tile * 64 + j, d = c >> 2, g = c & 3, sc = g * HID + d;
        float v = (k < EMBED) ? enc_wx[(size_t)k * G4 + sc]
                              : enc_wh[(size_t)(k - EMBED) * G4 + sc];
        d_Wenc[i] = __float2bfloat16(v);
    }
    // Wdec
    for (size_t i = g0; i < (size_t)T_DEC * 2048 * 64; i += gs) {
        int tile = (int)(i / 131072); int r = (int)(i % 131072);
        int k = r >> 6, j = r & 63;
        int c = tile * 64 + j, d = c >> 2, g = c & 3, sc = g * HID + d;
        float v = (k < HID) ? dec_wx[(size_t)k * G4 + sc]
                            : dec_wh[(size_t)(k - HID) * G4 + sc];
        d_Wdec[i] = __float2bfloat16(v);
    }
    // Wcmb (plain cols, tiled)
    for (size_t i = g0; i < (size_t)T_CMB * 2048 * 64; i += gs) {
        int tile = (int)(i / 131072); int r = (int)(i % 131072);
        int k = r >> 6, j = r & 63;
        d_Wcmb[i] = __float2bfloat16(comb_w[(size_t)k * HID + tile * 64 + j]);
    }
    // Wout (plain cols, tiled)
    for (size_t i = g0; i < (size_t)T_OUT * HID * 64; i += gs) {
        int tile = (int)(i >> 16); int r = (int)(i & 65535);
        int k = r >> 6, j = r & 63;
        d_Wout[i] = __float2bfloat16(out_w[(size_t)k * VOCAB + tile * 64 + j]);
    }
    // interleaved biases
    for (size_t i = g0; i < G4; i += gs) {
        int d = (int)(i >> 2), g = (int)(i & 3);
        d_benc[i] = enc_b[g * HID + d];
        d_bdec[i] = dec_b[g * HID + d];
    }
    // states + initial decoder embedding (token 127)
    for (size_t i = g0; i < BATCH * HID; i += gs) {
        d_g0[i] = 0.f; d_g1[i] = 0.f; d_ce[i] = 0.f;
        d_h0[i] = 0.f; d_h1[i] = 0.f; d_cd[i] = 0.f;
        d_ebuf[i] = dec_embed[(size_t)127 * HID + (i % HID)];
    }
    // gather encoder embeddings [t][b][e]
    for (size_t i = g0; i < (size_t)SEQL * BATCH * EMBED; i += gs) {
        int t = (int)(i / (BATCH * EMBED));
        int r = (int)(i % (BATCH * EMBED));
        int b = r / EMBED, d = r % EMBED;
        int tok = x[b * SEQL + t];
        d_Eenc[i] = enc_embed[(size_t)tok * EMBED + d];
    }
    if (g0 == 0) { g_bar = 0u; g_bar_enc = 0u; }
}

// ---------------- host launch ----------------
extern "C" void kernel_launch(void* const* d_in, const int* in_sizes, int n_in,
                              void* d_out, int out_size) {
    (void)in_sizes; (void)n_in; (void)out_size;
    const int*   x         = (const int*)d_in[0];
    const float* enc_embed = (const float*)d_in[1];
    const float* enc_wx    = (const float*)d_in[2];
    const float* enc_wh    = (const float*)d_in[3];
    const float* enc_b     = (const float*)d_in[4];
    const float* dec_embed = (const float*)d_in[5];
    const float* attn_w    = (const float*)d_in[6];
    const float* attn_b    = (const float*)d_in[7];
    const float* comb_w    = (const float*)d_in[8];
    const float* comb_b    = (const float*)d_in[9];
    const float* dec_wx    = (const float*)d_in[10];
    const float* dec_wh    = (const float*)d_in[11];
    const float* dec_b     = (const float*)d_in[12];
    const float* out_w     = (const float*)d_in[13];
    const float* out_b     = (const float*)d_in[14];
    float* out = (float*)d_out;

    cudaFuncSetAttribute(seq_kernel, cudaFuncAttributeMaxDynamicSharedMemorySize, SMEM_DYN);

    prep_kernel<<<2048, TPB>>>(x, enc_embed, enc_wx, enc_wh, enc_b, dec_embed,
                               comb_w, dec_wx, dec_wh, dec_b, out_w);
    seq_kernel<<<GRID, TPB, SMEM_DYN>>>(attn_w, attn_b, comb_b, out_b, dec_embed, out);
}

// round 9
// speedup vs baseline: 4.0630x; 1.2507x over previous
#include <cuda_runtime.h>
#include <cuda_bf16.h>
#include <mma.h>
#include <math.h>

using namespace nvcuda;

#define VOCAB 32000
#define EMBED 512
#define HID   1024      // DEC_H
#define SEQL  64
#define BATCH 32
#define G4    4096
#define GRID  148
#define TPB   256
#define PAD   8

#define T_ENC 64        // G4/64 tiles
#define T_DEC 64
#define T_CMB 16        // HID/64
#define T_OUT 500       // VOCAB/64

#define SMEM_DYN (32*(2*HID+PAD)*2 + 32*64*4)   // 131584 + 8192 = 139776

typedef __nv_bfloat16 bf16;

// ---------------- device scratch ----------------
__device__ bf16  d_Eenc[SEQL * BATCH * EMBED];        // [t][b][e] bf16
__device__ bf16  d_enc_outs[BATCH * SEQL * HID];      // [b][t][d] bf16
__device__ bf16  d_gb0[BATCH * HID], d_gb1[BATCH * HID];   // encoder h ping-pong (bf16)
__device__ float d_ce[BATCH * HID];
__device__ bf16  d_hb0[BATCH * HID], d_hb1[BATCH * HID];   // decoder h ping-pong (bf16)
__device__ float d_cd[BATCH * HID];
__device__ bf16  d_ebuf[BATCH * HID];
__device__ bf16  d_ctx[BATCH * HID];
__device__ bf16  d_inp[BATCH * HID];
__device__ float d_logits[(size_t)BATCH * VOCAB];
__device__ float d_benc[G4], d_bdec[G4];
__device__ float d_pm[BATCH * 512], d_ps[BATCH * 512];
__device__ int   d_pa[BATCH * 512];
__device__ float d_lse[BATCH];
__device__ unsigned g_bar;       // full-grid barrier counter
__device__ unsigned g_bar_enc;   // 64-block encoder barrier counter

__device__ bf16 d_attnT[SEQL * 2 * HID];              // attn_w transposed: [l][k] bf16

__device__ bf16 d_Wenc[(size_t)T_ENC * (EMBED + HID) * 64];  // [tile][k][64], gate-interleaved cols
__device__ bf16 d_Wdec[(size_t)T_DEC * (2 * HID) * 64];
__device__ bf16 d_Wcmb[(size_t)T_CMB * (2 * HID) * 64];
__device__ bf16 d_Wout[(size_t)T_OUT * HID * 64];

__device__ __forceinline__ float sigm(float x) { return 1.f / (1.f + expf(-x)); }

__device__ __forceinline__ float dot8(uint4 ua, uint4 uw) {
    float s = 0.f;
    const unsigned* a = (const unsigned*)&ua;
    const unsigned* w = (const unsigned*)&uw;
    #pragma unroll
    for (int j = 0; j < 4; j++) {
        float2 fa = __bfloat1622float2(*(const __nv_bfloat162*)&a[j]);
        float2 fw = __bfloat1622float2(*(const __nv_bfloat162*)&w[j]);
        s += fa.x * fw.x + fa.y * fw.y;
    }
    return s;
}

// ---------------- software barrier (all participating blocks co-resident) ----------------
__device__ __forceinline__ void sw_barrier(unsigned* ctr, unsigned& gen, unsigned nblk) {
    __threadfence();                       // release: my writes visible at L2
    __syncthreads();
    if (threadIdx.x == 0) {
        unsigned target = (gen + 1u) * nblk;
        atomicAdd(ctr, 1u);
        int it = 0;
        while (*((volatile unsigned*)ctr) < target) { if (++it > 64) __nanosleep(64); }
        __threadfence();                   // acquire: invalidate this SM's L1D
    }
    gen++;
    __syncthreads();
}

// ---------------- A staging: bf16 copy 32 x (K1+K2) -> smem, ldm = K+PAD ----------------
template<int K1, int K2>
__device__ __forceinline__ void stage_A(bf16* sA, const bf16* __restrict__ A1,
                                        const bf16* __restrict__ A2) {
    constexpr int K = K1 + K2;
    constexpr int tot = 32 * K / 8;
    for (int i = threadIdx.x; i < tot; i += TPB) {
        int m = i / (K / 8);
        int k = (i - m * (K / 8)) * 8;
        const bf16* s = (K2 == 0 || k < K1) ? (A1 + m * K1 + k) : (A2 + m * K2 + (k - K1));
        *(uint4*)(sA + m * (K + PAD) + k) = *(const uint4*)s;
    }
    __syncthreads();
}

// ---------------- GEMM tile: sC[32][64] = sA[32][K] @ Bt[K][64], prefetched fragments ----
template<int K>
__device__ __forceinline__ void gemm_tile(const bf16* sA,
                                          const bf16* __restrict__ Bt,
                                          float* sC) {
    constexpr int LDA = K + PAD;
    const int w = threadIdx.x >> 5;
    const int mh = w >> 2, nq = w & 3;
    wmma::fragment<wmma::matrix_a, 16, 16, 16, bf16, wmma::row_major> fa[4];
    wmma::fragment<wmma::matrix_b, 16, 16, 16, bf16, wmma::row_major> fb[4];
    wmma::fragment<wmma::accumulator, 16, 16, 16, float> acc0, acc1;
    wmma::fill_fragment(acc0, 0.f);
    wmma::fill_fragment(acc1, 0.f);
    const bf16* aRow = sA + mh * 16 * LDA;
    const bf16* bCol = Bt + nq * 16;
    #pragma unroll 4
    for (int c = 0; c < K; c += 64) {
        // issue all 16 B-loads (global/L2) + 4 A-loads (smem) before any mma
        #pragma unroll
        for (int j = 0; j < 4; j++)
            wmma::load_matrix_sync(fb[j], bCol + (size_t)(c + 16 * j) * 64, 64);
        #pragma unroll
        for (int j = 0; j < 4; j++)
            wmma::load_matrix_sync(fa[j], aRow + c + 16 * j, LDA);
        wmma::mma_sync(acc0, fa[0], fb[0], acc0);
        wmma::mma_sync(acc1, fa[1], fb[1], acc1);
        wmma::mma_sync(acc0, fa[2], fb[2], acc0);
        wmma::mma_sync(acc1, fa[3], fb[3], acc1);
    }
    #pragma unroll
    for (int i = 0; i < acc0.num_elements; i++) acc0.x[i] += acc1.x[i];
    wmma::store_matrix_sync(sC + mh * 16 * 64 + nq * 16, acc0, 64, wmma::mem_row_major);
    __syncthreads();
}

// ---------------- LSTM cell epilogue (interleaved gates, tile n0) ----------------
__device__ __forceinline__ void cell_epi(const float* sC, const float* bias, int n0,
                                         float* cbuf, bf16* hb, bf16* enc_out, int t) {
    for (int i = threadIdx.x; i < BATCH * 16; i += TPB) {
        int m = i >> 4, dd = i & 15, cb = dd * 4;
        float gi = sigm(sC[m * 64 + cb + 0] + bias[n0 + cb + 0]);
        float gf = sigm(sC[m * 64 + cb + 1] + bias[n0 + cb + 1]);
        float gg = tanhf(sC[m * 64 + cb + 2] + bias[n0 + cb + 2]);
        float go = sigm(sC[m * 64 + cb + 3] + bias[n0 + cb + 3]);
        int d = (n0 >> 2) + dd;
        int idx = m * HID + d;
        float c = gf * cbuf[idx] + gi * gg;
        float h = go * tanhf(c);
        cbuf[idx] = c;
        bf16 hb16 = __float2bfloat16(h);
        hb[idx] = hb16;
        if (enc_out) enc_out[((size_t)m * SEQL + t) * HID + d] = hb16;
    }
    __syncthreads();
}

// ---------------- out-projection epilogue: logits + online-softmax partials ----------------
__device__ __forceinline__ void epi_out(const float* sC, const float* __restrict__ out_b, int tile) {
    const int tid = threadIdx.x;
    const int r = tid >> 3, c0 = (tid & 7) * 8, n0 = tile * 64;
    float v[8];
    float pm = -INFINITY; int pa = 0;
    #pragma unroll
    for (int j = 0; j < 8; j++) {
        float x = sC[r * 64 + c0 + j] + out_b[n0 + c0 + j];
        v[j] = x;
        if (x > pm) { pm = x; pa = n0 + c0 + j; }
    }
    float4* dst = (float4*)(d_logits + (size_t)r * VOCAB + n0 + c0);
    dst[0] = make_float4(v[0], v[1], v[2], v[3]);
    dst[1] = make_float4(v[4], v[5], v[6], v[7]);
    float ps = 0.f;
    #pragma unroll
    for (int j = 0; j < 8; j++) ps += expf(v[j] - pm);
    #pragma unroll
    for (int o = 4; o > 0; o >>= 1) {
        float om = __shfl_xor_sync(0xffffffffu, pm, o);
        float os = __shfl_xor_sync(0xffffffffu, ps, o);
        int   oa = __shfl_xor_sync(0xffffffffu, pa, o);
        if (om > pm) { ps = ps * expf(pm - om) + os; pm = om; pa = oa; }
        else if (om == pm) { ps += os; if (oa < pa) pa = oa; }
        else ps += os * expf(om - pm);
    }
    if ((tid & 7) == 0) {
        d_pm[r * 512 + tile] = pm;
        d_ps[r * 512 + tile] = ps;
        d_pa[r * 512 + tile] = pa;
    }
    __syncthreads();
}

// ---------------- attention: logits + softmax + context for batch b (bf16 inputs) -------
__device__ void attn_phase(int b, const float* __restrict__ attn_b,
                           const bf16* __restrict__ hb, float* scratch) {
    float* aw = scratch;   // 64 floats
    const int tid = threadIdx.x;
    const int l = tid >> 2, part = tid & 3;
    const bf16* e = d_ebuf + b * HID;
    const bf16* h = hb + b * HID;
    const uint4* wrow = (const uint4*)(d_attnT + (size_t)l * 2 * HID + part * 512);
    const uint4* av = (const uint4*)((part < 2) ? (e + part * 512) : (h + (part - 2) * 512));
    float s = 0.f;
    #pragma unroll 8
    for (int i = 0; i < 64; i++) s += dot8(av[i], wrow[i]);
    s += __shfl_xor_sync(0xffffffffu, s, 1);
    s += __shfl_xor_sync(0xffffffffu, s, 2);
    if (part == 0) aw[l] = s + attn_b[l];
    __syncthreads();
    if (tid == 0) {
        float mx = -INFINITY;
        for (int j = 0; j < SEQL; j++) mx = fmaxf(mx, aw[j]);
        float sum = 0.f;
        for (int j = 0; j < SEQL; j++) { float ev = expf(aw[j] - mx); aw[j] = ev; sum += ev; }
        float inv = 1.f / sum;
        for (int j = 0; j < SEQL; j++) aw[j] *= inv;
    }
    __syncthreads();
    // ctx[d4..d4+3] = sum_l aw[l] * enc_outs[b][l][d4..]
    const bf16* eo = d_enc_outs + (size_t)b * SEQL * HID;
    const int d4 = tid * 4;
    float c0 = 0.f, c1 = 0.f, c2 = 0.f, c3 = 0.f;
    #pragma unroll 8
    for (int ll = 0; ll < SEQL; ll++) {
        float a = aw[ll];
        uint2 u = *(const uint2*)(eo + (size_t)ll * HID + d4);
        float2 p0 = __bfloat1622float2(*(const __nv_bfloat162*)&u.x);
        float2 p1 = __bfloat1622float2(*(const __nv_bfloat162*)&u.y);
        c0 += a * p0.x; c1 += a * p0.y; c2 += a * p1.x; c3 += a * p1.y;
    }
    __nv_bfloat162 o0 = __floats2bfloat162_rn(c0, c1);
    __nv_bfloat162 o1 = __floats2bfloat162_rn(c2, c3);
    uint2 uo; uo.x = *(unsigned*)&o0; uo.y = *(unsigned*)&o1;
    *(uint2*)(d_ctx + b * HID + d4) = uo;
    __syncthreads();
}

// ---------------- reduce partials -> lse, argmax token, gather next embedding ----------------
__device__ void reduce_phase(int b, const float* __restrict__ dec_embed, float* scratch) {
    const int tid = threadIdx.x;
    float* smax = scratch;
    float* ssum = scratch + 256;
    int*   sarg = (int*)(scratch + 512);
    int*   stok = (int*)(scratch + 768);
    float pm = -INFINITY, ps = 0.f; int pa = 0;
    for (int t = tid; t < T_OUT; t += TPB) {
        float om = d_pm[b * 512 + t], os = d_ps[b * 512 + t];
        int oa = d_pa[b * 512 + t];
        if (om > pm) { ps = ps * expf(pm - om) + os; pm = om; pa = oa; }
        else if (om == pm) { ps += os; if (oa < pa) pa = oa; }
        else ps += os * expf(om - pm);
    }
    smax[tid] = pm; ssum[tid] = ps; sarg[tid] = pa;
    __syncthreads();
    for (int st = 128; st > 0; st >>= 1) {
        if (tid < st) {
            float om = smax[tid + st], os = ssum[tid + st]; int oa = sarg[tid + st];
            float cm = smax[tid],      cs = ssum[tid];      int ca = sarg[tid];
            if (om > cm) { cs = cs * expf(cm - om) + os; cm = om; ca = oa; }
            else if (om == cm) { cs += os; if (oa < ca) ca = oa; }
            else cs += os * expf(om - cm);
            smax[tid] = cm; ssum[tid] = cs; sarg[tid] = ca;
        }
        __syncthreads();
    }
    if (tid == 0) { d_lse[b] = smax[0] + logf(ssum[0]); stok[0] = sarg[0]; }
    __syncthreads();
    int token = stok[0];
    for (int d = tid; d < HID; d += TPB)
        d_ebuf[b * HID + d] = __float2bfloat16(dec_embed[(size_t)token * HID + d]);
    __syncthreads();
}

// ---------------- distributed log-p write ----------------
__device__ void fixup_logp(int step, float* __restrict__ out, int bfirst, int nblocks) {
    int lb = blockIdx.x - bfirst;
    const int tot = BATCH * (VOCAB / 4);
    for (int i = lb * TPB + threadIdx.x; i < tot; i += nblocks * TPB) {
        int b = i / (VOCAB / 4);
        int q = i - b * (VOCAB / 4);
        float4 f = ((const float4*)(d_logits + (size_t)b * VOCAB))[q];
        float lse = d_lse[b];
        f.x -= lse; f.y -= lse; f.z -= lse; f.w -= lse;
        ((float4*)(out + ((size_t)b * SEQL + step) * VOCAB))[q] = f;
    }
}

// ---------------- persistent kernel ----------------
__global__ __launch_bounds__(TPB, 1) void seq_kernel(
    const float* __restrict__ attn_b,
    const float* __restrict__ comb_b, const float* __restrict__ out_b,
    const float* __restrict__ dec_embed, float* __restrict__ out)
{
    extern __shared__ unsigned char dynmem[];
    bf16* sA = (bf16*)dynmem;
    float* sC = (float*)(dynmem + 32 * (2 * HID + PAD) * 2);
    float* scratch = (float*)sA;
    unsigned gen = 0, gen_enc = 0;
    const int bid = blockIdx.x;

    // ---- encoder: blocks 0-63, sub-barrier of 64 ----
    if (bid < T_ENC) {
        for (int t = 0; t < SEQL; t++) {
            const bf16* hr = (t & 1) ? d_gb1 : d_gb0;
            bf16*       hw = (t & 1) ? d_gb0 : d_gb1;
            stage_A<EMBED, HID>(sA, d_Eenc + (size_t)t * BATCH * EMBED, hr);
            gemm_tile<EMBED + HID>(sA, d_Wenc + (size_t)bid * (EMBED + HID) * 64, sC);
            cell_epi(sC, d_benc, bid * 64, d_ce, hw, d_enc_outs, t);
            sw_barrier(&g_bar_enc, gen_enc, T_ENC);
        }
    }
    sw_barrier(&g_bar, gen, GRID);

    // ---- decoder ----
    for (int s = 0; s < SEQL; s++) {
        const bf16* hr = (s & 1) ? d_hb1 : d_hb0;
        bf16*       hw = (s & 1) ? d_hb0 : d_hb1;
        // phase EA: reduce(s-1) + attention(s) on blocks 0-31
        if (bid < BATCH) {
            if (s > 0) reduce_phase(bid, dec_embed, scratch);
            attn_phase(bid, attn_b, hr, scratch);
        }
        sw_barrier(&g_bar, gen, GRID);
        // phase B: combine (0-15) || logp fixup of step s-1 (16-147)
        if (bid < T_CMB) {
            stage_A<HID, HID>(sA, d_ebuf, d_ctx);
            gemm_tile<2 * HID>(sA, d_Wcmb + (size_t)bid * (2 * HID) * 64, sC);
            int n0 = bid * 64;
            for (int i = threadIdx.x; i < BATCH * 64; i += TPB) {
                int m = i >> 6, j = i & 63;
                float v = sC[m * 64 + j] + comb_b[n0 + j];
                d_inp[m * HID + n0 + j] = __float2bfloat16(fmaxf(v, 0.f));
            }
            __syncthreads();
        } else if (s > 0) {
            fixup_logp(s - 1, out, T_CMB, GRID - T_CMB);
        }
        sw_barrier(&g_bar, gen, GRID);
        // phase C: decoder LSTM gates + cell
        if (bid < T_DEC) {
            stage_A<HID, HID>(sA, d_inp, hr);
            gemm_tile<2 * HID>(sA, d_Wdec + (size_t)bid * (2 * HID) * 64, sC);
            cell_epi(sC, d_bdec, bid * 64, d_cd, hw, nullptr, 0);
        }
        sw_barrier(&g_bar, gen, GRID);
        // phase D: out projection (all blocks)
        stage_A<HID, 0>(sA, hw, nullptr);
        for (int tile = bid; tile < T_OUT; tile += GRID) {
            gemm_tile<HID>(sA, d_Wout + (size_t)tile * HID * 64, sC);
            epi_out(sC, out_b, tile);
        }
        sw_barrier(&g_bar, gen, GRID);
    }
    // tail
    if (bid < BATCH) reduce_phase(bid, dec_embed, scratch);
    sw_barrier(&g_bar, gen, GRID);
    fixup_logp(SEQL - 1, out, 0, GRID);
}

// ---------------- prep ----------------
__global__ void prep_kernel(
    const int* __restrict__ x, const float* __restrict__ enc_embed,
    const float* __restrict__ enc_wx, const float* __restrict__ enc_wh,
    const float* __restrict__ enc_b, const float* __restrict__ dec_embed,
    const float* __restrict__ attn_w, const float* __restrict__ comb_w,
    const float* __restrict__ dec_wx, const float* __restrict__ dec_wh,
    const float* __restrict__ dec_b, const float* __restrict__ out_w)
{
    const size_t gs = (size_t)gridDim.x * blockDim.x;
    const size_t g0 = (size_t)blockIdx.x * blockDim.x + threadIdx.x;

    // Wenc: tiled + gate-interleaved
    for (size_t i = g0; i < (size_t)T_ENC * 1536 * 64; i += gs) {
        int tile = (int)(i / 98304); int r = (int)(i % 98304);
        int k = r >> 6, j = r & 63;
        int c = tile * 64 + j, d = c >> 2, g = c & 3, sc = g * HID + d;
        float v = (k < EMBED) ? enc_wx[(size_t)k * G4 + sc]
                              : enc_wh[(size_t)(k - EMBED) * G4 + sc];
        d_Wenc[i] = __float2bfloat16(v);
    }
    // Wdec
    for (size_t i = g0; i < (size_t)T_DEC * 2048 * 64; i += gs) {
        int tile = (int)(i / 131072); int r = (int)(i % 131072);
        int k = r >> 6, j = r & 63;
        int c = tile * 64 + j, d = c >> 2, g = c & 3, sc = g * HID + d;
        float v = (k < HID) ? dec_wx[(size_t)k * G4 + sc]
                            : dec_wh[(size_t)(k - HID) * G4 + sc];
        d_Wdec[i] = __float2bfloat16(v);
    }
    // Wcmb
    for (size_t i = g0; i < (size_t)T_CMB * 2048 * 64; i += gs) {
        int tile = (int)(i / 131072); int r = (int)(i % 131072);
        int k = r >> 6, j = r & 63;
        d_Wcmb[i] = __float2bfloat16(comb_w[(size_t)k * HID + tile * 64 + j]);
    }
    // Wout
    for (size_t i = g0; i < (size_t)T_OUT * HID * 64; i += gs) {
        int tile = (int)(i >> 16); int r = (int)(i & 65535);
        int k = r >> 6, j = r & 63;
        d_Wout[i] = __float2bfloat16(out_w[(size_t)k * VOCAB + tile * 64 + j]);
    }
    // attn_w transpose -> [l][k] bf16
    for (size_t i = g0; i < (size_t)SEQL * 2 * HID; i += gs) {
        int l = (int)(i >> 11), k = (int)(i & 2047);
        d_attnT[i] = __float2bfloat16(attn_w[(size_t)k * SEQL + l]);
    }
    // interleaved biases
    for (size_t i = g0; i < G4; i += gs) {
        int d = (int)(i >> 2), g = (int)(i & 3);
        d_benc[i] = enc_b[g * HID + d];
        d_bdec[i] = dec_b[g * HID + d];
    }
    // states + initial decoder embedding (token 127)
    for (size_t i = g0; i < BATCH * HID; i += gs) {
        bf16 z = __float2bfloat16(0.f);
        d_gb0[i] = z; d_gb1[i] = z; d_ce[i] = 0.f;
        d_hb0[i] = z; d_hb1[i] = z; d_cd[i] = 0.f;
        d_ebuf[i] = __float2bfloat16(dec_embed[(size_t)127 * HID + (i % HID)]);
    }
    // gather encoder embeddings [t][b][e] bf16
    for (size_t i = g0; i < (size_t)SEQL * BATCH * EMBED; i += gs) {
        int t = (int)(i / (BATCH * EMBED));
        int r = (int)(i % (BATCH * EMBED));
        int b = r / EMBED, d = r % EMBED;
        int tok = x[b * SEQL + t];
        d_Eenc[i] = __float2bfloat16(enc_embed[(size_t)tok * EMBED + d]);
    }
    if (g0 == 0) { g_bar = 0u; g_bar_enc = 0u; }
}

// ---------------- host launch ----------------
extern "C" void kernel_launch(void* const* d_in, const int* in_sizes, int n_in,
                              void* d_out, int out_size) {
    (void)in_sizes; (void)n_in; (void)out_size;
    const int*   x         = (const int*)d_in[0];
    const float* enc_embed = (const float*)d_in[1];
    const float* enc_wx    = (const float*)d_in[2];
    const float* enc_wh    = (const float*)d_in[3];
    const float* enc_b     = (const float*)d_in[4];
    const float* dec_embed = (const float*)d_in[5];
    const float* attn_w    = (const float*)d_in[6];
    const float* attn_b    = (const float*)d_in[7];
    const float* comb_w    = (const float*)d_in[8];
    const float* comb_b    = (const float*)d_in[9];
    const float* dec_wx    = (const float*)d_in[10];
    const float* dec_wh    = (const float*)d_in[11];
    const float* dec_b     = (const float*)d_in[12];
    const float* out_w     = (const float*)d_in[13];
    const float* out_b     = (const float*)d_in[14];
    float* out = (float*)d_out;

    cudaFuncSetAttribute(seq_kernel, cudaFuncAttributeMaxDynamicSharedMemorySize, SMEM_DYN);

    prep_kernel<<<2048, TPB>>>(x, enc_embed, enc_wx, enc_wh, enc_b, dec_embed,
                               attn_w, comb_w, dec_wx, dec_wh, dec_b, out_w);
    seq_kernel<<<GRID, TPB, SMEM_DYN>>>(attn_b, comb_b, out_b, dec_embed, out);
}

// round 10
// speedup vs baseline: 6.4915x; 1.5977x over previous
#include <cuda_runtime.h>
#include <cuda_bf16.h>
#include <mma.h>
#include <math.h>

using namespace nvcuda;

#define VOCAB 32000
#define EMBED 512
#define HID   1024      // DEC_H
#define SEQL  64
#define BATCH 32
#define G4    4096
#define GRID  148
#define TPB   256
#define PAD   8

#define T_ENC 64        // G4/64 tiles
#define T_DEC 64
#define T_CMB 16        // HID/64
#define T_OUT 500       // VOCAB/64

#define BSTG  5         // B pipeline stages
#define BLD   72        // padded B stage ld (bank-conflict-free)

// fixed smem layout (bytes): sA [0,131584) | sB [131584,177664) | sC [177664,185856)
#define SA_BYTES 131584
#define SB_BYTES (BSTG * 64 * BLD * 2)     // 46080
#define SMEM_DYN (SA_BYTES + SB_BYTES + 32 * 64 * 4)

typedef __nv_bfloat16 bf16;

// ---------------- device scratch ----------------
__device__ bf16  d_Eenc[SEQL * BATCH * EMBED];        // [t][b][e] bf16
__device__ bf16  d_enc_outs[BATCH * SEQL * HID];      // [b][t][d] bf16
__device__ bf16  d_gb0[BATCH * HID], d_gb1[BATCH * HID];   // encoder h ping-pong (bf16)
__device__ float d_ce[BATCH * HID];
__device__ bf16  d_hb0[BATCH * HID], d_hb1[BATCH * HID];   // decoder h ping-pong (bf16)
__device__ float d_cd[BATCH * HID];
__device__ bf16  d_ebuf[BATCH * HID];
__device__ bf16  d_ctx[BATCH * HID];
__device__ bf16  d_inp[BATCH * HID];
__device__ float d_logits[(size_t)BATCH * VOCAB];
__device__ float d_benc[G4], d_bdec[G4];
__device__ float d_pm[BATCH * 512], d_ps[BATCH * 512];
__device__ int   d_pa[BATCH * 512];
__device__ float d_lse[BATCH];
__device__ unsigned g_bar;       // full-grid barrier counter
__device__ unsigned g_bar_enc;   // 64-block encoder barrier counter

__device__ bf16 d_attnT[SEQL * 2 * HID];              // attn_w transposed: [l][k] bf16

__device__ bf16 d_Wenc[(size_t)T_ENC * (EMBED + HID) * 64];  // [tile][k][64], gate-interleaved cols
__device__ bf16 d_Wdec[(size_t)T_DEC * (2 * HID) * 64];
__device__ bf16 d_Wcmb[(size_t)T_CMB * (2 * HID) * 64];
__device__ bf16 d_Wout[(size_t)T_OUT * HID * 64];

__device__ __forceinline__ float sigm(float x) { return 1.f / (1.f + expf(-x)); }

__device__ __forceinline__ float dot8(uint4 ua, uint4 uw) {
    float s = 0.f;
    const unsigned* a = (const unsigned*)&ua;
    const unsigned* w = (const unsigned*)&uw;
    #pragma unroll
    for (int j = 0; j < 4; j++) {
        float2 fa = __bfloat1622float2(*(const __nv_bfloat162*)&a[j]);
        float2 fw = __bfloat1622float2(*(const __nv_bfloat162*)&w[j]);
        s += fa.x * fw.x + fa.y * fw.y;
    }
    return s;
}

// ---------------- cp.async helpers ----------------
__device__ __forceinline__ void cp_async16(bf16* smem_dst, const bf16* gmem_src) {
    unsigned d = (unsigned)__cvta_generic_to_shared(smem_dst);
    asm volatile("cp.async.cg.shared.global [%0], [%1], 16;\n" :: "r"(d), "l"(gmem_src));
}
__device__ __forceinline__ void cp_commit() { asm volatile("cp.async.commit_group;\n"); }
template<int N>
__device__ __forceinline__ void cp_wait() { asm volatile("cp.async.wait_group %0;\n" :: "n"(N)); }

// ---------------- software barrier ----------------
__device__ __forceinline__ void sw_barrier(unsigned* ctr, unsigned& gen, unsigned nblk) {
    __threadfence();                       // release
    __syncthreads();
    if (threadIdx.x == 0) {
        unsigned target = (gen + 1u) * nblk;
        atomicAdd(ctr, 1u);
        int it = 0;
        while (*((volatile unsigned*)ctr) < target) { if (++it > 64) __nanosleep(64); }
        __threadfence();                   // acquire: invalidate this SM's L1D
    }
    gen++;
    __syncthreads();
}

// ---------------- A staging: bf16 copy 32 x (K1+K2) -> smem, ldm = K+PAD ----------------
template<int K1, int K2>
__device__ __forceinline__ void stage_A(bf16* sA, const bf16* __restrict__ A1,
                                        const bf16* __restrict__ A2) {
    constexpr int K = K1 + K2;
    constexpr int tot = 32 * K / 8;
    for (int i = threadIdx.x; i < tot; i += TPB) {
        int m = i / (K / 8);
        int k = (i - m * (K / 8)) * 8;
        const bf16* s = (K2 == 0 || k < K1) ? (A1 + m * K1 + k) : (A2 + m * K2 + (k - K1));
        *(uint4*)(sA + m * (K + PAD) + k) = *(const uint4*)s;
    }
    __syncthreads();
}

// ---------------- B chunk copy: 64 rows x 64 cols bf16 -> stage (512 x 16B) ----------------
__device__ __forceinline__ void copy_B_chunk(bf16* dst, const bf16* __restrict__ src) {
    const int tid = threadIdx.x;
    #pragma unroll
    for (int i = 0; i < 2; i++) {
        int idx = tid + i * 256;
        int r = idx >> 3, cq = idx & 7;
        cp_async16(dst + r * BLD + cq * 8, src + (size_t)r * 64 + cq * 8);
    }
}

// ---------------- GEMM tile with cp.async pipelined B: sC[32][64] = sA[32][K] @ Bt[K][64] ----
template<int K>
__device__ __forceinline__ void gemm_tile(const bf16* sA, const bf16* __restrict__ Bt,
                                          float* sC, bf16* sB) {
    constexpr int LDA = K + PAD;
    constexpr int NCH = K / 64;
    const int w = threadIdx.x >> 5;
    const int mh = w >> 2, nq = w & 3;

    // prologue: chunks 0..2
    #pragma unroll
    for (int st = 0; st < 3; st++) {
        copy_B_chunk(sB + st * (64 * BLD), Bt + (size_t)st * 64 * 64);
        cp_commit();
    }

    wmma::fragment<wmma::matrix_a, 16, 16, 16, bf16, wmma::row_major> fa;
    wmma::fragment<wmma::matrix_b, 16, 16, 16, bf16, wmma::row_major> fb;
    wmma::fragment<wmma::accumulator, 16, 16, 16, float> acc0, acc1;
    wmma::fill_fragment(acc0, 0.f);
    wmma::fill_fragment(acc1, 0.f);

    int slot = 0;
    for (int c = 0; c < NCH; c++) {
        if (c + 3 < NCH)
            copy_B_chunk(sB + ((c + 3) % BSTG) * (64 * BLD), Bt + (size_t)(c + 3) * 64 * 64);
        cp_commit();
        cp_wait<3>();          // chunk c's group complete
        __syncthreads();       // all threads' copies visible; also fences slot reuse (5 stages, lookahead 3)
        const bf16* bst = sB + slot * (64 * BLD) + nq * 16;
        const bf16* ast = sA + mh * 16 * LDA + c * 64;
        wmma::load_matrix_sync(fa, ast, LDA);
        wmma::load_matrix_sync(fb, bst, BLD);
        wmma::mma_sync(acc0, fa, fb, acc0);
        wmma::load_matrix_sync(fa, ast + 16, LDA);
        wmma::load_matrix_sync(fb, bst + 16 * BLD, BLD);
        wmma::mma_sync(acc1, fa, fb, acc1);
        wmma::load_matrix_sync(fa, ast + 32, LDA);
        wmma::load_matrix_sync(fb, bst + 32 * BLD, BLD);
        wmma::mma_sync(acc0, fa, fb, acc0);
        wmma::load_matrix_sync(fa, ast + 48, LDA);
        wmma::load_matrix_sync(fb, bst + 48 * BLD, BLD);
        wmma::mma_sync(acc1, fa, fb, acc1);
        if (++slot == BSTG) slot = 0;
    }
    cp_wait<0>();
    #pragma unroll
    for (int i = 0; i < acc0.num_elements; i++) acc0.x[i] += acc1.x[i];
    wmma::store_matrix_sync(sC + mh * 16 * 64 + nq * 16, acc0, 64, wmma::mem_row_major);
    __syncthreads();
}

// ---------------- LSTM cell epilogue (interleaved gates, tile n0) ----------------
__device__ __forceinline__ void cell_epi(const float* sC, const float* bias, int n0,
                                         float* cbuf, bf16* hb, bf16* enc_out, int t) {
    for (int i = threadIdx.x; i < BATCH * 16; i += TPB) {
        int m = i >> 4, dd = i & 15, cb = dd * 4;
        float gi = sigm(sC[m * 64 + cb + 0] + bias[n0 + cb + 0]);
        float gf = sigm(sC[m * 64 + cb + 1] + bias[n0 + cb + 1]);
        float gg = tanhf(sC[m * 64 + cb + 2] + bias[n0 + cb + 2]);
        float go = sigm(sC[m * 64 + cb + 3] + bias[n0 + cb + 3]);
        int d = (n0 >> 2) + dd;
        int idx = m * HID + d;
        float c = gf * cbuf[idx] + gi * gg;
        float h = go * tanhf(c);
        cbuf[idx] = c;
        bf16 hb16 = __float2bfloat16(h);
        hb[idx] = hb16;
        if (enc_out) enc_out[((size_t)m * SEQL + t) * HID + d] = hb16;
    }
    __syncthreads();
}

// ---------------- out-projection epilogue: logits + online-softmax partials ----------------
__device__ __forceinline__ void epi_out(const float* sC, const float* __restrict__ out_b, int tile) {
    const int tid = threadIdx.x;
    const int r = tid >> 3, c0 = (tid & 7) * 8, n0 = tile * 64;
    float v[8];
    float pm = -INFINITY; int pa = 0;
    #pragma unroll
    for (int j = 0; j < 8; j++) {
        float x = sC[r * 64 + c0 + j] + out_b[n0 + c0 + j];
        v[j] = x;
        if (x > pm) { pm = x; pa = n0 + c0 + j; }
    }
    float4* dst = (float4*)(d_logits + (size_t)r * VOCAB + n0 + c0);
    dst[0] = make_float4(v[0], v[1], v[2], v[3]);
    dst[1] = make_float4(v[4], v[5], v[6], v[7]);
    float ps = 0.f;
    #pragma unroll
    for (int j = 0; j < 8; j++) ps += expf(v[j] - pm);
    #pragma unroll
    for (int o = 4; o > 0; o >>= 1) {
        float om = __shfl_xor_sync(0xffffffffu, pm, o);
        float os = __shfl_xor_sync(0xffffffffu, ps, o);
        int   oa = __shfl_xor_sync(0xffffffffu, pa, o);
        if (om > pm) { ps = ps * expf(pm - om) + os; pm = om; pa = oa; }
        else if (om == pm) { ps += os; if (oa < pa) pa = oa; }
        else ps += os * expf(om - pm);
    }
    if ((tid & 7) == 0) {
        d_pm[r * 512 + tile] = pm;
        d_ps[r * 512 + tile] = ps;
        d_pa[r * 512 + tile] = pa;
    }
    __syncthreads();
}

// ---------------- attention: logits + softmax + context for batch b (bf16 inputs) -------
__device__ void attn_phase(int b, const float* __restrict__ attn_b,
                           const bf16* __restrict__ hb, float* scratch) {
    float* aw = scratch;   // 64 floats
    const int tid = threadIdx.x;
    const int l = tid >> 2, part = tid & 3;
    const bf16* e = d_ebuf + b * HID;
    const bf16* h = hb + b * HID;
    const uint4* wrow = (const uint4*)(d_attnT + (size_t)l * 2 * HID + part * 512);
    const uint4* av = (const uint4*)((part < 2) ? (e + part * 512) : (h + (part - 2) * 512));
    float s = 0.f;
    #pragma unroll 8
    for (int i = 0; i < 64; i++) s += dot8(av[i], wrow[i]);
    s += __shfl_xor_sync(0xffffffffu, s, 1);
    s += __shfl_xor_sync(0xffffffffu, s, 2);
    if (part == 0) aw[l] = s + attn_b[l];
    __syncthreads();
    if (tid == 0) {
        float mx = -INFINITY;
        for (int j = 0; j < SEQL; j++) mx = fmaxf(mx, aw[j]);
        float sum = 0.f;
        for (int j = 0; j < SEQL; j++) { float ev = expf(aw[j] - mx); aw[j] = ev; sum += ev; }
        float inv = 1.f / sum;
        for (int j = 0; j < SEQL; j++) aw[j] *= inv;
    }
    __syncthreads();
    const bf16* eo = d_enc_outs + (size_t)b * SEQL * HID;
    const int d4 = tid * 4;
    float c0 = 0.f, c1 = 0.f, c2 = 0.f, c3 = 0.f;
    #pragma unroll 8
    for (int ll = 0; ll < SEQL; ll++) {
        float a = aw[ll];
        uint2 u = *(const uint2*)(eo + (size_t)ll * HID + d4);
        float2 p0 = __bfloat1622float2(*(const __nv_bfloat162*)&u.x);
        float2 p1 = __bfloat1622float2(*(const __nv_bfloat162*)&u.y);
        c0 += a * p0.x; c1 += a * p0.y; c2 += a * p1.x; c3 += a * p1.y;
    }
    __nv_bfloat162 o0 = __floats2bfloat162_rn(c0, c1);
    __nv_bfloat162 o1 = __floats2bfloat162_rn(c2, c3);
    uint2 uo; uo.x = *(unsigned*)&o0; uo.y = *(unsigned*)&o1;
    *(uint2*)(d_ctx + b * HID + d4) = uo;
    __syncthreads();
}

// ---------------- reduce partials -> lse, argmax token, gather next embedding ----------------
__device__ void reduce_phase(int b, const float* __restrict__ dec_embed, float* scratch) {
    const int tid = threadIdx.x;
    float* smax = scratch;
    float* ssum = scratch + 256;
    int*   sarg = (int*)(scratch + 512);
    int*   stok = (int*)(scratch + 768);
    float pm = -INFINITY, ps = 0.f; int pa = 0;
    for (int t = tid; t < T_OUT; t += TPB) {
        float om = d_pm[b * 512 + t], os = d_ps[b * 512 + t];
        int oa = d_pa[b * 512 + t];
        if (om > pm) { ps = ps * expf(pm - om) + os; pm = om; pa = oa; }
        else if (om == pm) { ps += os; if (oa < pa) pa = oa; }
        else ps += os * expf(om - pm);
    }
    smax[tid] = pm; ssum[tid] = ps; sarg[tid] = pa;
    __syncthreads();
    for (int st = 128; st > 0; st >>= 1) {
        if (tid < st) {
            float om = smax[tid + st], os = ssum[tid + st]; int oa = sarg[tid + st];
            float cm = smax[tid],      cs = ssum[tid];      int ca = sarg[tid];
            if (om > cm) { cs = cs * expf(cm - om) + os; cm = om; ca = oa; }
            else if (om == cm) { cs += os; if (oa < ca) ca = oa; }
            else cs += os * expf(om - cm);
            smax[tid] = cm; ssum[tid] = cs; sarg[tid] = ca;
        }
        __syncthreads();
    }
    if (tid == 0) { d_lse[b] = smax[0] + logf(ssum[0]); stok[0] = sarg[0]; }
    __syncthreads();
    int token = stok[0];
    for (int d = tid; d < HID; d += TPB)
        d_ebuf[b * HID + d] = __float2bfloat16(dec_embed[(size_t)token * HID + d]);
    __syncthreads();
}

// ---------------- distributed log-p write ----------------
__device__ void fixup_logp(int step, float* __restrict__ out, int bfirst, int nblocks) {
    int lb = blockIdx.x - bfirst;
    const int tot = BATCH * (VOCAB / 4);
    for (int i = lb * TPB + threadIdx.x; i < tot; i += nblocks * TPB) {
        int b = i / (VOCAB / 4);
        int q = i - b * (VOCAB / 4);
        float4 f = ((const float4*)(d_logits + (size_t)b * VOCAB))[q];
        float lse = d_lse[b];
        f.x -= lse; f.y -= lse; f.z -= lse; f.w -= lse;
        ((float4*)(out + ((size_t)b * SEQL + step) * VOCAB))[q] = f;
    }
}

// ---------------- persistent kernel ----------------
__global__ __launch_bounds__(TPB, 1) void seq_kernel(
    const float* __restrict__ attn_b,
    const float* __restrict__ comb_b, const float* __restrict__ out_b,
    const float* __restrict__ dec_embed, float* __restrict__ out)
{
    extern __shared__ unsigned char dynmem[];
    bf16*  sA = (bf16*)dynmem;
    bf16*  sB = (bf16*)(dynmem + SA_BYTES);
    float* sC = (float*)(dynmem + SA_BYTES + SB_BYTES);
    float* scratch = (float*)sA;
    unsigned gen = 0, gen_enc = 0;
    const int bid = blockIdx.x;

    // ---- encoder: blocks 0-63, sub-barrier of 64 ----
    if (bid < T_ENC) {
        for (int t = 0; t < SEQL; t++) {
            const bf16* hr = (t & 1) ? d_gb1 : d_gb0;
            bf16*       hw = (t & 1) ? d_gb0 : d_gb1;
            stage_A<EMBED, HID>(sA, d_Eenc + (size_t)t * BATCH * EMBED, hr);
            gemm_tile<EMBED + HID>(sA, d_Wenc + (size_t)bid * (EMBED + HID) * 64, sC, sB);
            cell_epi(sC, d_benc, bid * 64, d_ce, hw, d_enc_outs, t);
            sw_barrier(&g_bar_enc, gen_enc, T_ENC);
        }
    }
    sw_barrier(&g_bar, gen, GRID);

    // ---- decoder ----
    for (int s = 0; s < SEQL; s++) {
        const bf16* hr = (s & 1) ? d_hb1 : d_hb0;
        bf16*       hw = (s & 1) ? d_hb0 : d_hb1;
        // phase EA: reduce(s-1) + attention(s) on blocks 0-31
        if (bid < BATCH) {
            if (s > 0) reduce_phase(bid, dec_embed, scratch);
            attn_phase(bid, attn_b, hr, scratch);
        }
        sw_barrier(&g_bar, gen, GRID);
        // phase B: combine (0-15) || logp fixup of step s-1 (16-147)
        if (bid < T_CMB) {
            stage_A<HID, HID>(sA, d_ebuf, d_ctx);
            gemm_tile<2 * HID>(sA, d_Wcmb + (size_t)bid * (2 * HID) * 64, sC, sB);
            int n0 = bid * 64;
            for (int i = threadIdx.x; i < BATCH * 64; i += TPB) {
                int m = i >> 6, j = i & 63;
                float v = sC[m * 64 + j] + comb_b[n0 + j];
                d_inp[m * HID + n0 + j] = __float2bfloat16(fmaxf(v, 0.f));
            }
            __syncthreads();
        } else if (s > 0) {
            fixup_logp(s - 1, out, T_CMB, GRID - T_CMB);
        }
        sw_barrier(&g_bar, gen, GRID);
        // phase C: decoder LSTM gates + cell
        if (bid < T_DEC) {
            stage_A<HID, HID>(sA, d_inp, hr);
            gemm_tile<2 * HID>(sA, d_Wdec + (size_t)bid * (2 * HID) * 64, sC, sB);
            cell_epi(sC, d_bdec, bid * 64, d_cd, hw, nullptr, 0);
        }
        sw_barrier(&g_bar, gen, GRID);
        // phase D: out projection (all blocks)
        stage_A<HID, 0>(sA, hw, nullptr);
        for (int tile = bid; tile < T_OUT; tile += GRID) {
            gemm_tile<HID>(sA, d_Wout + (size_t)tile * HID * 64, sC, sB);
            epi_out(sC, out_b, tile);
        }
        sw_barrier(&g_bar, gen, GRID);
    }
    // tail
    if (bid < BATCH) reduce_phase(bid, dec_embed, scratch);
    sw_barrier(&g_bar, gen, GRID);
    fixup_logp(SEQL - 1, out, 0, GRID);
}

// ---------------- prep ----------------
__global__ void prep_kernel(
    const int* __restrict__ x, const float* __restrict__ enc_embed,
    const float* __restrict__ enc_wx, const float* __restrict__ enc_wh,
    const float* __restrict__ enc_b, const float* __restrict__ dec_embed,
    const float* __restrict__ attn_w, const float* __restrict__ comb_w,
    const float* __restrict__ dec_wx, const float* __restrict__ dec_wh,
    const float* __restrict__ dec_b, const float* __restrict__ out_w)
{
    const size_t gs = (size_t)gridDim.x * blockDim.x;
    const size_t g0 = (size_t)blockIdx.x * blockDim.x + threadIdx.x;

    for (size_t i = g0; i < (size_t)T_ENC * 1536 * 64; i += gs) {
        int tile = (int)(i / 98304); int r = (int)(i % 98304);
        int k = r >> 6, j = r & 63;
        int c = tile * 64 + j, d = c >> 2, g = c & 3, sc = g * HID + d;
        float v = (k < EMBED) ? enc_wx[(size_t)k * G4 + sc]
                              : enc_wh[(size_t)(k - EMBED) * G4 + sc];
        d_Wenc[i] = __float2bfloat16(v);
    }
    for (size_t i = g0; i < (size_t)T_DEC * 2048 * 64; i += gs) {
        int tile = (int)(i / 131072); int r = (int)(i % 131072);
        int k = r >> 6, j = r & 63;
        int c = tile * 64 + j, d = c >> 2, g = c & 3, sc = g * HID + d;
        float v = (k < HID) ? dec_wx[(size_t)k * G4 + sc]
                            : dec_wh[(size_t)(k - HID) * G4 + sc];
        d_Wdec[i] = __float2bfloat16(v);
    }
    for (size_t i = g0; i < (size_t)T_CMB * 2048 * 64; i += gs) {
        int tile = (int)(i / 131072); int r = (int)(i % 131072);
        int k = r >> 6, j = r & 63;
        d_Wcmb[i] = __float2bfloat16(comb_w[(size_t)k * HID + tile * 64 + j]);
    }
    for (size_t i = g0; i < (size_t)T_OUT * HID * 64; i += gs) {
        int tile = (int)(i >> 16); int r = (int)(i & 65535);
        int k = r >> 6, j = r & 63;
        d_Wout[i] = __float2bfloat16(out_w[(size_t)k * VOCAB + tile * 64 + j]);
    }
    for (size_t i = g0; i < (size_t)SEQL * 2 * HID; i += gs) {
        int l = (int)(i >> 11), k = (int)(i & 2047);
        d_attnT[i] = __float2bfloat16(attn_w[(size_t)k * SEQL + l]);
    }
    for (size_t i = g0; i < G4; i += gs) {
        int d = (int)(i >> 2), g = (int)(i & 3);
        d_benc[i] = enc_b[g * HID + d];
        d_bdec[i] = dec_b[g * HID + d];
    }
    for (size_t i = g0; i < BATCH * HID; i += gs) {
        bf16 z = __float2bfloat16(0.f);
        d_gb0[i] = z; d_gb1[i] = z; d_ce[i] = 0.f;
        d_hb0[i] = z; d_hb1[i] = z; d_cd[i] = 0.f;
        d_ebuf[i] = __float2bfloat16(dec_embed[(size_t)127 * HID + (i % HID)]);
    }
    for (size_t i = g0; i < (size_t)SEQL * BATCH * EMBED; i += gs) {
        int t = (int)(i / (BATCH * EMBED));
        int r = (int)(i % (BATCH * EMBED));
        int b = r / EMBED, d = r % EMBED;
        int tok = x[b * SEQL + t];
        d_Eenc[i] = __float2bfloat16(enc_embed[(size_t)tok * EMBED + d]);
    }
    if (g0 == 0) { g_bar = 0u; g_bar_enc = 0u; }
}

// ---------------- host launch ----------------
extern "C" void kernel_launch(void* const* d_in, const int* in_sizes, int n_in,
                              void* d_out, int out_size) {
    (void)in_sizes; (void)n_in; (void)out_size;
    const int*   x         = (const int*)d_in[0];
    const float* enc_embed = (const float*)d_in[1];
    const float* enc_wx    = (const float*)d_in[2];
    const float* enc_wh    = (const float*)d_in[3];
    const float* enc_b     = (const float*)d_in[4];
    const float* dec_embed = (const float*)d_in[5];
    const float* attn_w    = (const float*)d_in[6];
    const float* attn_b    = (const float*)d_in[7];
    const float* comb_w    = (const float*)d_in[8];
    const float* comb_b    = (const float*)d_in[9];
    const float* dec_wx    = (const float*)d_in[10];
    const float* dec_wh    = (const float*)d_in[11];
    const float* dec_b     = (const float*)d_in[12];
    const float* out_w     = (const float*)d_in[13];
    const float* out_b     = (const float*)d_in[14];
    float* out = (float*)d_out;

    cudaFuncSetAttribute(seq_kernel, cudaFuncAttributeMaxDynamicSharedMemorySize, SMEM_DYN);

    prep_kernel<<<2048, TPB>>>(x, enc_embed, enc_wx, enc_wh, enc_b, dec_embed,
                               attn_w, comb_w, dec_wx, dec_wh, dec_b, out_w);
    seq_kernel<<<GRID, TPB, SMEM_DYN>>>(attn_b, comb_b, out_b, dec_embed, out);
}